// round 10
// baseline (speedup 1.0000x reference)
#include <cuda_runtime.h>

// ---------------------------------------------------------------------------
// GraphRNNDecoder rollout. N=4096 rows, T=128 steps, D=4, H=256.
// R9 (= R8 resubmit after infra failure): 256 persistent CTAs x 512 threads,
// 16 rows per CTA -> 2 co-resident CTAs per SM (independent barrier domains)
// to hide weight-LDG latency and barrier drains. Lane = output unit
// (coalesced weight LDG), h via full-broadcast LDS. All 16 warps active in
// every phase.
// ---------------------------------------------------------------------------

#define T_STEPS 128
#define DIN     4
#define HID     256
#define G4      1024
#define MROWS   16
#define NCTA    256
#define NTHR    512
#define KC      64
#define RP      20            // row pad (floats) per unit

// k-chunk packed weights [kc][unit] -> float4 of W[unit][4kc..4kc+3]
__device__ float4 g_whh[KC * G4];   // 1 MB
__device__ float4 g_fc1[KC * HID];  // 256 KB
__device__ float4 g_fc2[KC * HID];  // 256 KB

__global__ void pack_kernel(const float* __restrict__ W_hh,
                            const float* __restrict__ fc1_w,
                            const float* __restrict__ fc2_w) {
    int i = blockIdx.x * blockDim.x + threadIdx.x;
    if (i < KC * G4) {
        int kc = i >> 10, j = i & 1023;
        g_whh[i] = *reinterpret_cast<const float4*>(W_hh + j * HID + kc * 4);
    }
    if (i < KC * HID) {
        int kc = i >> 8, j = i & 255;
        g_fc1[i] = *reinterpret_cast<const float4*>(fc1_w + j * HID + kc * 4);
        g_fc2[i] = *reinterpret_cast<const float4*>(fc2_w + j * HID + kc * 4);
    }
}

// ---- packed f32x2 helpers --------------------------------------------------
__device__ __forceinline__ unsigned long long pk2(float lo, float hi) {
    unsigned long long r;
    asm("mov.b64 %0, {%1, %2};" : "=l"(r) : "f"(lo), "f"(hi));
    return r;
}
__device__ __forceinline__ void fma2(unsigned long long& d,
                                     unsigned long long a,
                                     unsigned long long b) {
    asm("fma.rn.f32x2 %0, %1, %2, %0;" : "+l"(d) : "l"(a), "l"(b));
}
__device__ __forceinline__ void unpk2(unsigned long long v, float& lo, float& hi) {
    asm("mov.b64 {%0, %1}, %2;" : "=f"(lo), "=f"(hi) : "l"(v));
}
__device__ __forceinline__ float sigf(float x) {
    return __fdividef(1.0f, 1.0f + __expf(-x));
}
__device__ __forceinline__ float tanhf_fast(float x) {
    float e = __expf(2.0f * x);
    return 1.0f - __fdividef(2.0f, e + 1.0f);
}

// ---- shared layout (float offsets) -----------------------------------------
#define SBUF      (HID * RP)    // 5120: one [256][RP] activation buffer
#define OFF_BUF   0             // 3 buffers: h ping, h pong, p2
#define OFF_C     15360         // [256][RP] c state
#define OFF_PREV  20480         // [16][4]
#define OFF_WIH   20544         // [1024][4]
#define OFF_BG    24640         // [1024]
#define OFF_FB1   25664         // [256]
#define OFF_FB2   25920         // [256]
#define OFF_FC3   26176         // [256][4]  fc3T[k][d]
#define OFF_B3    27200         // [4]
#define SMEM_FLOATS 27204
#define SMEM_BYTES  (SMEM_FLOATS * 4)

// fc phase: all 16 warps; thread = unit jf x 8 rows (rf0..rf0+7)
__device__ __forceinline__ void fc_phase(const float* __restrict__ src,
                                         float* __restrict__ dst,
                                         const float4* __restrict__ wbase,
                                         const float* __restrict__ bsh,
                                         int jf, int rf0) {
    unsigned long long acc[4];
    {
        float b0 = bsh[jf];
        acc[0] = acc[1] = acc[2] = acc[3] = pk2(b0, b0);
    }
#pragma unroll 1
    for (int kc = 0; kc < KC; kc++) {
        // broadcast h loads: all lanes of warp read identical addresses
        const float* hb = src + kc * (4 * RP) + rf0;
        ulonglong2 h[4][2];
#pragma unroll
        for (int kk = 0; kk < 4; kk++) {
            h[kk][0] = *reinterpret_cast<const ulonglong2*>(hb + kk * RP);
            h[kk][1] = *reinterpret_cast<const ulonglong2*>(hb + kk * RP + 4);
        }
        float4 wv = wbase[kc * HID + jf];   // lane-distinct, coalesced
#pragma unroll
        for (int kk = 0; kk < 4; kk++) {
            float wk = (kk == 0) ? wv.x : (kk == 1) ? wv.y : (kk == 2) ? wv.z : wv.w;
            unsigned long long w2 = pk2(wk, wk);
            fma2(acc[0], w2, h[kk][0].x);
            fma2(acc[1], w2, h[kk][0].y);
            fma2(acc[2], w2, h[kk][1].x);
            fma2(acc[3], w2, h[kk][1].y);
        }
    }
    float v0, v1, v2, v3, v4, v5, v6, v7;
    unpk2(acc[0], v0, v1); unpk2(acc[1], v2, v3);
    unpk2(acc[2], v4, v5); unpk2(acc[3], v6, v7);
    *reinterpret_cast<float4*>(dst + jf * RP + rf0) =
        make_float4(fmaxf(v0, 0.f), fmaxf(v1, 0.f), fmaxf(v2, 0.f), fmaxf(v3, 0.f));
    *reinterpret_cast<float4*>(dst + jf * RP + rf0 + 4) =
        make_float4(fmaxf(v4, 0.f), fmaxf(v5, 0.f), fmaxf(v6, 0.f), fmaxf(v7, 0.f));
}

__global__ void __launch_bounds__(NTHR, 2)
rnn_rollout_kernel(const float* __restrict__ inputs,
                   const float* __restrict__ W_ih,
                   const float* __restrict__ b_ih,
                   const float* __restrict__ b_hh,
                   const float* __restrict__ fc1_b,
                   const float* __restrict__ fc2_b,
                   const float* __restrict__ fc3_w,
                   const float* __restrict__ fc3_b,
                   float* __restrict__ out) {
    extern __shared__ float sm[];
    float* buf    = sm + OFF_BUF;
    float* csh    = sm + OFF_C;
    float* prevsh = sm + OFF_PREV;
    float* wihsh  = sm + OFF_WIH;
    float* bgsh   = sm + OFF_BG;
    float* fb1sh  = sm + OFF_FB1;
    float* fb2sh  = sm + OFF_FB2;
    float* fc3T   = sm + OFF_FC3;
    float* b3sh   = sm + OFF_B3;

    const int tid  = threadIdx.x;
    const int w    = tid >> 5;           // warp 0..15
    const int l    = tid & 31;
    // phase A / elementwise / fc mapping: 256 units x 2 rowgroups of 8
    const int j2   = (w & 7) * 32 + l;   // 0..255
    const int rg   = w >> 3;             // 0..1
    const int r0   = rg * 8;
    const int row0 = blockIdx.x * MROWS;

    // ---- one-time init ----
    for (int i = tid; i < G4; i += NTHR) {
        *reinterpret_cast<float4*>(wihsh + i * 4) =
            *reinterpret_cast<const float4*>(W_ih + i * 4);
        bgsh[i] = b_ih[i] + b_hh[i];
        fc3T[i] = fc3_w[(i & 3) * HID + (i >> 2)];
    }
    if (tid < HID) { fb1sh[tid] = fc1_b[tid]; fb2sh[tid] = fc2_b[tid]; }
    if (tid < DIN) b3sh[tid] = fc3_b[tid];
    for (int i = tid; i < 3 * SBUF; i += NTHR) buf[i] = 0.0f;
    for (int i = tid; i < SBUF; i += NTHR) csh[i] = 0.0f;
    if (tid < MROWS * DIN)
        prevsh[tid] = inputs[((size_t)(row0 + (tid >> 2)) * T_STEPS) * DIN + (tid & 3)];
    __syncthreads();

    for (int t = 0; t < T_STEPS; t++) {
        const int par = t & 1;
        float* hin  = buf + par * SBUF;
        float* hout = buf + (par ^ 1) * SBUF;
        float* p1   = hin;                 // fc1 overwrites dead h_in
        float* p2   = buf + 2 * SBUF;

        // ---- phase A: gate GEMM. thread = j2 x 4 gates x 8 rows ----
        unsigned long long acc[4][4];
        {
#pragma unroll
            for (int g = 0; g < 4; g++) {
                float4 wg = *reinterpret_cast<const float4*>(wihsh + (g * 256 + j2) * 4);
                float b = bgsh[g * 256 + j2];
#pragma unroll
                for (int p = 0; p < 4; p++) {
                    float4 pa = *reinterpret_cast<const float4*>(prevsh + 4 * (r0 + 2 * p));
                    float4 pb = *reinterpret_cast<const float4*>(prevsh + 4 * (r0 + 2 * p + 1));
                    acc[g][p] = pk2(b + wg.x*pa.x + wg.y*pa.y + wg.z*pa.z + wg.w*pa.w,
                                    b + wg.x*pb.x + wg.y*pb.y + wg.z*pb.z + wg.w*pb.w);
                }
            }
        }
#pragma unroll 1
        for (int kc = 0; kc < KC; kc++) {
            // broadcast h: 8 rows x 4 k-values, identical across lanes
            const float* hb = hin + kc * (4 * RP) + r0;
            ulonglong2 h[4][2];
#pragma unroll
            for (int kk = 0; kk < 4; kk++) {
                h[kk][0] = *reinterpret_cast<const ulonglong2*>(hb + kk * RP);
                h[kk][1] = *reinterpret_cast<const ulonglong2*>(hb + kk * RP + 4);
            }
            const float4* wk = g_whh + kc * G4 + j2;
#pragma unroll
            for (int g = 0; g < 4; g++) {
                float4 wv = wk[g * 256];           // lane-distinct, coalesced
#pragma unroll
                for (int kk = 0; kk < 4; kk++) {
                    float wkk = (kk == 0) ? wv.x : (kk == 1) ? wv.y : (kk == 2) ? wv.z : wv.w;
                    unsigned long long w2 = pk2(wkk, wkk);
                    fma2(acc[g][0], w2, h[kk][0].x);
                    fma2(acc[g][1], w2, h[kk][0].y);
                    fma2(acc[g][2], w2, h[kk][1].x);
                    fma2(acc[g][3], w2, h[kk][1].y);
                }
            }
        }
        // ---- fused LSTM elementwise: (j2, rows r0..r0+7) ----
        {
            float4 cv0 = *reinterpret_cast<const float4*>(csh + j2 * RP + r0);
            float4 cv1 = *reinterpret_cast<const float4*>(csh + j2 * RP + r0 + 4);
            float cc[8] = {cv0.x, cv0.y, cv0.z, cv0.w, cv1.x, cv1.y, cv1.z, cv1.w};
            float hh[8];
#pragma unroll
            for (int p = 0; p < 4; p++) {
                float i0, i1, f0, f1, g0, g1, o0, o1;
                unpk2(acc[0][p], i0, i1);
                unpk2(acc[1][p], f0, f1);
                unpk2(acc[2][p], g0, g1);
                unpk2(acc[3][p], o0, o1);
                float c0 = sigf(f0) * cc[2*p]   + sigf(i0) * tanhf_fast(g0);
                float c1 = sigf(f1) * cc[2*p+1] + sigf(i1) * tanhf_fast(g1);
                cc[2*p]   = c0;
                cc[2*p+1] = c1;
                hh[2*p]   = sigf(o0) * tanhf_fast(c0);
                hh[2*p+1] = sigf(o1) * tanhf_fast(c1);
            }
            *reinterpret_cast<float4*>(csh + j2 * RP + r0)     = make_float4(cc[0], cc[1], cc[2], cc[3]);
            *reinterpret_cast<float4*>(csh + j2 * RP + r0 + 4) = make_float4(cc[4], cc[5], cc[6], cc[7]);
            *reinterpret_cast<float4*>(hout + j2 * RP + r0)     = make_float4(hh[0], hh[1], hh[2], hh[3]);
            *reinterpret_cast<float4*>(hout + j2 * RP + r0 + 4) = make_float4(hh[4], hh[5], hh[6], hh[7]);
        }
        __syncthreads();

        // ---- fc1: hout -> p1 ----
        fc_phase(hout, p1, g_fc1, fb1sh, j2, r0);
        __syncthreads();

        // ---- fc2: p1 -> p2 ----
        fc_phase(p1, p2, g_fc2, fb2sh, j2, r0);
        __syncthreads();

        // ---- fc3 + residual: warp w = row w (16 warps) ----
        {
            const int row = w;
            const int d   = l & 3;
            const int s   = l >> 2;
            const float* pp = p2 + row;
            float a0 = 0.f;
#pragma unroll 8
            for (int i = 0; i < 32; i++) {
                const int k = i * 8 + s;
                a0 = fmaf(pp[k * RP], fc3T[k * 4 + d], a0);
            }
            a0 += __shfl_xor_sync(0xffffffffu, a0, 4);
            a0 += __shfl_xor_sync(0xffffffffu, a0, 8);
            a0 += __shfl_xor_sync(0xffffffffu, a0, 16);
            if (s == 0) {
                float r = a0 + b3sh[d] + prevsh[row * 4 + d];
                out[((size_t)(row0 + row) * T_STEPS + t) * DIN + d] = r;
                prevsh[row * 4 + d] = r;
            }
        }
        __syncthreads();
    }
}

extern "C" void kernel_launch(void* const* d_in, const int* in_sizes, int n_in,
                              void* d_out, int out_size) {
    const float* inputs = (const float*)d_in[0];
    const float* W_ih   = (const float*)d_in[1];
    const float* W_hh   = (const float*)d_in[2];
    const float* b_ih   = (const float*)d_in[3];
    const float* b_hh   = (const float*)d_in[4];
    const float* fc1_w  = (const float*)d_in[5];
    const float* fc1_b  = (const float*)d_in[6];
    const float* fc2_w  = (const float*)d_in[7];
    const float* fc2_b  = (const float*)d_in[8];
    const float* fc3_w  = (const float*)d_in[9];
    const float* fc3_b  = (const float*)d_in[10];
    float* out = (float*)d_out;

    const int pack_total = KC * G4;
    pack_kernel<<<(pack_total + NTHR - 1) / NTHR, NTHR>>>(W_hh, fc1_w, fc2_w);

    cudaFuncSetAttribute(rnn_rollout_kernel,
                         cudaFuncAttributeMaxDynamicSharedMemorySize, SMEM_BYTES);
    rnn_rollout_kernel<<<NCTA, NTHR, SMEM_BYTES>>>(
        inputs, W_ih, b_ih, b_hh, fc1_b, fc2_b, fc3_w, fc3_b, out);
}

// round 13
// speedup vs baseline: 1.1680x; 1.1680x over previous
#include <cuda_runtime.h>

// ---------------------------------------------------------------------------
// GraphRNNDecoder rollout. N=4096 rows, T=128 steps, D=4, H=256.
// 128 persistent CTAs x 1024 threads, 32 rows per CTA (R6 base, best=14.19ms).
// R12 (third submit of R10 after broker failures): latency-tolerant inner
// loops. Weight LDGs issued first (MLP=4, pointer-bumped), h LDS consumed
// kk-sliced (live regs 16->4), unroll 2 so ptxas overlaps next-kc loads with
// current-kc FMAs within the 64-reg cap.
// ---------------------------------------------------------------------------

#define T_STEPS 128
#define DIN     4
#define HID     256
#define G4      1024
#define MROWS   32
#define NCTA    128
#define KC      64

// k-chunk packed weights [kc][unit] -> float4 of W[unit][4kc..4kc+3]
__device__ float4 g_whh[KC * G4];   // 1 MB
__device__ float4 g_fc1[KC * HID];  // 256 KB
__device__ float4 g_fc2[KC * HID];  // 256 KB

__global__ void pack_kernel(const float* __restrict__ W_hh,
                            const float* __restrict__ fc1_w,
                            const float* __restrict__ fc2_w) {
    int i = blockIdx.x * blockDim.x + threadIdx.x;
    if (i < KC * G4) {
        int kc = i >> 10, j = i & 1023;
        g_whh[i] = *reinterpret_cast<const float4*>(W_hh + j * HID + kc * 4);
    }
    if (i < KC * HID) {
        int kc = i >> 8, j = i & 255;
        g_fc1[i] = *reinterpret_cast<const float4*>(fc1_w + j * HID + kc * 4);
        g_fc2[i] = *reinterpret_cast<const float4*>(fc2_w + j * HID + kc * 4);
    }
}

// ---- packed f32x2 helpers --------------------------------------------------
__device__ __forceinline__ unsigned long long pk2(float lo, float hi) {
    unsigned long long r;
    asm("mov.b64 %0, {%1, %2};" : "=l"(r) : "f"(lo), "f"(hi));
    return r;
}
__device__ __forceinline__ void fma2(unsigned long long& d,
                                     unsigned long long a,
                                     unsigned long long b) {
    asm("fma.rn.f32x2 %0, %1, %2, %0;" : "+l"(d) : "l"(a), "l"(b));
}
__device__ __forceinline__ void unpk2(unsigned long long v, float& lo, float& hi) {
    asm("mov.b64 {%0, %1}, %2;" : "=f"(lo), "=f"(hi) : "l"(v));
}
__device__ __forceinline__ float sigf(float x) {
    return __fdividef(1.0f, 1.0f + __expf(-x));
}
__device__ __forceinline__ float tanhf_fast(float x) {
    float e = __expf(2.0f * x);
    return 1.0f - __fdividef(2.0f, e + 1.0f);
}

// ---- shared layout (float offsets) -----------------------------------------
#define SBUF      9216          // one [256][36] activation buffer
#define OFF_BUF   0             // 3 buffers: h ping, h pong, p2
#define OFF_C     27648         // [256][36] c state
#define OFF_PREV  36864         // [32][4]
#define OFF_WIH   36992         // [1024][4]
#define OFF_BG    41088         // [1024]
#define OFF_FB1   42112         // [256]
#define OFF_FB2   42368         // [256]
#define OFF_FC3   42624         // [256][4]  fc3T[k][d]
#define OFF_B3    43648         // [4]
#define SMEM_FLOATS 43652
#define SMEM_BYTES  (SMEM_FLOATS * 4)

// fc phase: 16 active warps; thread = units (jf, jf+32) x 8 rows (rf0..rf0+7)
// Weights-first schedule, kk-sliced h, pointer-bumped, unroll 2.
__device__ __forceinline__ void fc_phase(const float* __restrict__ src,
                                         float* __restrict__ dst,
                                         const float4* __restrict__ wbase,
                                         const float* __restrict__ bsh,
                                         int jf, int rf0) {
    unsigned long long acc[2][4];
    {
        float b0 = bsh[jf], b1 = bsh[jf + 32];
        acc[0][0] = acc[0][1] = acc[0][2] = acc[0][3] = pk2(b0, b0);
        acc[1][0] = acc[1][1] = acc[1][2] = acc[1][3] = pk2(b1, b1);
    }
    const float4* wp = wbase + jf;
    const float*  hp = src + rf0;
#pragma unroll 2
    for (int kc = 0; kc < KC; kc++) {
        // weights first: 2 independent LDGs, long distance to use
        float4 w0 = wp[0];
        float4 w1 = wp[32];
        wp += HID;
#pragma unroll
        for (int kk = 0; kk < 4; kk++) {
            ulonglong2 hA = *reinterpret_cast<const ulonglong2*>(hp + kk * 36);
            ulonglong2 hB = *reinterpret_cast<const ulonglong2*>(hp + kk * 36 + 4);
            float a0 = (kk == 0) ? w0.x : (kk == 1) ? w0.y : (kk == 2) ? w0.z : w0.w;
            float a1 = (kk == 0) ? w1.x : (kk == 1) ? w1.y : (kk == 2) ? w1.z : w1.w;
            unsigned long long u0 = pk2(a0, a0);
            unsigned long long u1 = pk2(a1, a1);
            fma2(acc[0][0], u0, hA.x); fma2(acc[0][1], u0, hA.y);
            fma2(acc[0][2], u0, hB.x); fma2(acc[0][3], u0, hB.y);
            fma2(acc[1][0], u1, hA.x); fma2(acc[1][1], u1, hA.y);
            fma2(acc[1][2], u1, hB.x); fma2(acc[1][3], u1, hB.y);
        }
        hp += 144;
    }
#pragma unroll
    for (int u = 0; u < 2; u++) {
        const int j = jf + u * 32;
        float v0, v1, v2, v3, v4, v5, v6, v7;
        unpk2(acc[u][0], v0, v1); unpk2(acc[u][1], v2, v3);
        unpk2(acc[u][2], v4, v5); unpk2(acc[u][3], v6, v7);
        *reinterpret_cast<float4*>(dst + j * 36 + rf0) =
            make_float4(fmaxf(v0, 0.f), fmaxf(v1, 0.f), fmaxf(v2, 0.f), fmaxf(v3, 0.f));
        *reinterpret_cast<float4*>(dst + j * 36 + rf0 + 4) =
            make_float4(fmaxf(v4, 0.f), fmaxf(v5, 0.f), fmaxf(v6, 0.f), fmaxf(v7, 0.f));
    }
}

__global__ void __launch_bounds__(1024, 1)
rnn_rollout_kernel(const float* __restrict__ inputs,
                   const float* __restrict__ W_ih,
                   const float* __restrict__ b_ih,
                   const float* __restrict__ b_hh,
                   const float* __restrict__ fc1_b,
                   const float* __restrict__ fc2_b,
                   const float* __restrict__ fc3_w,
                   const float* __restrict__ fc3_b,
                   float* __restrict__ out) {
    extern __shared__ float sm[];
    float* buf    = sm + OFF_BUF;
    float* csh    = sm + OFF_C;
    float* prevsh = sm + OFF_PREV;
    float* wihsh  = sm + OFF_WIH;
    float* bgsh   = sm + OFF_BG;
    float* fb1sh  = sm + OFF_FB1;
    float* fb2sh  = sm + OFF_FB2;
    float* fc3T   = sm + OFF_FC3;
    float* b3sh   = sm + OFF_B3;

    const int tid  = threadIdx.x;
    const int w    = tid >> 5;
    const int l    = tid & 31;
    // phase A / elementwise mapping: warp = 32 consecutive j2 x 1 rowgroup
    const int j2   = (w & 7) * 32 + l;   // 0..255
    const int rg   = w >> 3;             // 0..3
    const int r0   = rg * 8;
    // fc mapping (warps 0..15): thread = units (jf, jf+32) x rows rf0..rf0+7
    const int jf   = (w & 3) * 64 + l;
    const int rf0  = (w >> 2) * 8;
    const int row0 = blockIdx.x * MROWS;

    // ---- one-time init ----
    *reinterpret_cast<float4*>(wihsh + tid * 4) =
        *reinterpret_cast<const float4*>(W_ih + tid * 4);
    bgsh[tid] = b_ih[tid] + b_hh[tid];
    if (tid < HID) { fb1sh[tid] = fc1_b[tid]; fb2sh[tid] = fc2_b[tid]; }
    fc3T[tid] = fc3_w[(tid & 3) * HID + (tid >> 2)];
    if (tid < DIN) b3sh[tid] = fc3_b[tid];
    for (int i = tid; i < 3 * SBUF; i += 1024) buf[i] = 0.0f;
    for (int i = tid; i < SBUF; i += 1024) csh[i] = 0.0f;
    if (tid < MROWS * DIN)
        prevsh[tid] = inputs[((size_t)(row0 + (tid >> 2)) * T_STEPS) * DIN + (tid & 3)];
    __syncthreads();

    for (int t = 0; t < T_STEPS; t++) {
        const int par = t & 1;
        float* hin  = buf + par * SBUF;
        float* hout = buf + (par ^ 1) * SBUF;
        float* p1   = hin;                 // fc1 overwrites dead h_in
        float* p2   = buf + 2 * SBUF;

        // ---- phase A: gate GEMM. thread = j2 x 4 gates x 8 rows ----
        unsigned long long acc[4][4];
        {
#pragma unroll
            for (int g = 0; g < 4; g++) {
                float4 wg = *reinterpret_cast<const float4*>(wihsh + (g * 256 + j2) * 4);
                float b = bgsh[g * 256 + j2];
#pragma unroll
                for (int p = 0; p < 4; p++) {
                    float4 pa = *reinterpret_cast<const float4*>(prevsh + 4 * (r0 + 2 * p));
                    float4 pb = *reinterpret_cast<const float4*>(prevsh + 4 * (r0 + 2 * p + 1));
                    acc[g][p] = pk2(b + wg.x*pa.x + wg.y*pa.y + wg.z*pa.z + wg.w*pa.w,
                                    b + wg.x*pb.x + wg.y*pb.y + wg.z*pb.z + wg.w*pb.w);
                }
            }
        }
        {
            const float4* gw = g_whh + j2;
            const float*  hp = hin + r0;
#pragma unroll 2
            for (int kc = 0; kc < KC; kc++) {
                // weights first: 4 independent coalesced LDG.128 (MLP=4)
                float4 wv0 = gw[0];
                float4 wv1 = gw[256];
                float4 wv2 = gw[512];
                float4 wv3 = gw[768];
                gw += G4;
                // h consumed kk-sliced (4 live regs instead of 16)
#pragma unroll
                for (int kk = 0; kk < 4; kk++) {
                    ulonglong2 hA = *reinterpret_cast<const ulonglong2*>(hp + kk * 36);
                    ulonglong2 hB = *reinterpret_cast<const ulonglong2*>(hp + kk * 36 + 4);
                    float a0 = (kk == 0) ? wv0.x : (kk == 1) ? wv0.y : (kk == 2) ? wv0.z : wv0.w;
                    float a1 = (kk == 0) ? wv1.x : (kk == 1) ? wv1.y : (kk == 2) ? wv1.z : wv1.w;
                    float a2 = (kk == 0) ? wv2.x : (kk == 1) ? wv2.y : (kk == 2) ? wv2.z : wv2.w;
                    float a3 = (kk == 0) ? wv3.x : (kk == 1) ? wv3.y : (kk == 2) ? wv3.z : wv3.w;
                    unsigned long long u0 = pk2(a0, a0);
                    unsigned long long u1 = pk2(a1, a1);
                    unsigned long long u2 = pk2(a2, a2);
                    unsigned long long u3 = pk2(a3, a3);
                    fma2(acc[0][0], u0, hA.x); fma2(acc[0][1], u0, hA.y);
                    fma2(acc[0][2], u0, hB.x); fma2(acc[0][3], u0, hB.y);
                    fma2(acc[1][0], u1, hA.x); fma2(acc[1][1], u1, hA.y);
                    fma2(acc[1][2], u1, hB.x); fma2(acc[1][3], u1, hB.y);
                    fma2(acc[2][0], u2, hA.x); fma2(acc[2][1], u2, hA.y);
                    fma2(acc[2][2], u2, hB.x); fma2(acc[2][3], u2, hB.y);
                    fma2(acc[3][0], u3, hA.x); fma2(acc[3][1], u3, hA.y);
                    fma2(acc[3][2], u3, hB.x); fma2(acc[3][3], u3, hB.y);
                }
                hp += 144;
            }
        }
        // ---- fused LSTM elementwise: (j2, rows r0..r0+7) ----
        {
            float4 cv0 = *reinterpret_cast<const float4*>(csh + j2 * 36 + r0);
            float4 cv1 = *reinterpret_cast<const float4*>(csh + j2 * 36 + r0 + 4);
            float cc[8] = {cv0.x, cv0.y, cv0.z, cv0.w, cv1.x, cv1.y, cv1.z, cv1.w};
            float hh[8];
#pragma unroll
            for (int p = 0; p < 4; p++) {
                float i0, i1, f0, f1, g0, g1, o0, o1;
                unpk2(acc[0][p], i0, i1);
                unpk2(acc[1][p], f0, f1);
                unpk2(acc[2][p], g0, g1);
                unpk2(acc[3][p], o0, o1);
                float c0 = sigf(f0) * cc[2*p]   + sigf(i0) * tanhf_fast(g0);
                float c1 = sigf(f1) * cc[2*p+1] + sigf(i1) * tanhf_fast(g1);
                cc[2*p]   = c0;
                cc[2*p+1] = c1;
                hh[2*p]   = sigf(o0) * tanhf_fast(c0);
                hh[2*p+1] = sigf(o1) * tanhf_fast(c1);
            }
            *reinterpret_cast<float4*>(csh + j2 * 36 + r0)     = make_float4(cc[0], cc[1], cc[2], cc[3]);
            *reinterpret_cast<float4*>(csh + j2 * 36 + r0 + 4) = make_float4(cc[4], cc[5], cc[6], cc[7]);
            *reinterpret_cast<float4*>(hout + j2 * 36 + r0)     = make_float4(hh[0], hh[1], hh[2], hh[3]);
            *reinterpret_cast<float4*>(hout + j2 * 36 + r0 + 4) = make_float4(hh[4], hh[5], hh[6], hh[7]);
        }
        __syncthreads();

        // ---- fc1: hout -> p1 (warps 0..15) ----
        if (w < 16) fc_phase(hout, p1, g_fc1, fb1sh, jf, rf0);
        __syncthreads();

        // ---- fc2: p1 -> p2 (warps 0..15) ----
        if (w < 16) fc_phase(p1, p2, g_fc2, fb2sh, jf, rf0);
        __syncthreads();

        // ---- fc3 + residual: warp w = row w (32 warps) ----
        {
            const int row = w;
            const int d   = l & 3;
            const int s   = l >> 2;
            const float* pp = p2 + row;
            float a0 = 0.f;
#pragma unroll 8
            for (int i = 0; i < 32; i++) {
                const int k = i * 8 + s;
                a0 = fmaf(pp[k * 36], fc3T[k * 4 + d], a0);
            }
            a0 += __shfl_xor_sync(0xffffffffu, a0, 4);
            a0 += __shfl_xor_sync(0xffffffffu, a0, 8);
            a0 += __shfl_xor_sync(0xffffffffu, a0, 16);
            if (s == 0) {
                float r = a0 + b3sh[d] + prevsh[row * 4 + d];
                out[((size_t)(row0 + row) * T_STEPS + t) * DIN + d] = r;
                prevsh[row * 4 + d] = r;
            }
        }
        __syncthreads();
    }
}

extern "C" void kernel_launch(void* const* d_in, const int* in_sizes, int n_in,
                              void* d_out, int out_size) {
    const float* inputs = (const float*)d_in[0];
    const float* W_ih   = (const float*)d_in[1];
    const float* W_hh   = (const float*)d_in[2];
    const float* b_ih   = (const float*)d_in[3];
    const float* b_hh   = (const float*)d_in[4];
    const float* fc1_w  = (const float*)d_in[5];
    const float* fc1_b  = (const float*)d_in[6];
    const float* fc2_w  = (const float*)d_in[7];
    const float* fc2_b  = (const float*)d_in[8];
    const float* fc3_w  = (const float*)d_in[9];
    const float* fc3_b  = (const float*)d_in[10];
    float* out = (float*)d_out;

    const int pack_threads = 256;
    const int pack_total   = KC * G4;
    pack_kernel<<<(pack_total + pack_threads - 1) / pack_threads, pack_threads>>>(
        W_hh, fc1_w, fc2_w);

    cudaFuncSetAttribute(rnn_rollout_kernel,
                         cudaFuncAttributeMaxDynamicSharedMemorySize, SMEM_BYTES);
    rnn_rollout_kernel<<<NCTA, 1024, SMEM_BYTES>>>(
        inputs, W_ih, b_ih, b_hh, fc1_b, fc2_b, fc3_w, fc3_b, out);
}

// round 14
// speedup vs baseline: 1.3999x; 1.1985x over previous
#include <cuda_runtime.h>

// ---------------------------------------------------------------------------
// GraphRNNDecoder rollout. N=4096 rows, T=128 steps, D=4, H=256.
// R14: 128 persistent CTAs x 512 threads (~128 regs/thread, full RF),
// 32 rows per CTA. Phase A thread = 1 unit x 4 gates x 16 rows: weight-LDG
// and pk2-MOV density per FMA halved vs R12; phase A now FMA-bound
// (L1 ~768 wf vs 1024 FMA-cyc per kc window). fc phases keep R12 mapping.
// ---------------------------------------------------------------------------

#define T_STEPS 128
#define DIN     4
#define HID     256
#define G4      1024
#define MROWS   32
#define NCTA    128
#define NTHR    512
#define KC      64

// k-chunk packed weights [kc][unit] -> float4 of W[unit][4kc..4kc+3]
__device__ float4 g_whh[KC * G4];   // 1 MB
__device__ float4 g_fc1[KC * HID];  // 256 KB
__device__ float4 g_fc2[KC * HID];  // 256 KB

__global__ void pack_kernel(const float* __restrict__ W_hh,
                            const float* __restrict__ fc1_w,
                            const float* __restrict__ fc2_w) {
    int i = blockIdx.x * blockDim.x + threadIdx.x;
    if (i < KC * G4) {
        int kc = i >> 10, j = i & 1023;
        g_whh[i] = *reinterpret_cast<const float4*>(W_hh + j * HID + kc * 4);
    }
    if (i < KC * HID) {
        int kc = i >> 8, j = i & 255;
        g_fc1[i] = *reinterpret_cast<const float4*>(fc1_w + j * HID + kc * 4);
        g_fc2[i] = *reinterpret_cast<const float4*>(fc2_w + j * HID + kc * 4);
    }
}

// ---- packed f32x2 helpers --------------------------------------------------
__device__ __forceinline__ unsigned long long pk2(float lo, float hi) {
    unsigned long long r;
    asm("mov.b64 %0, {%1, %2};" : "=l"(r) : "f"(lo), "f"(hi));
    return r;
}
__device__ __forceinline__ void fma2(unsigned long long& d,
                                     unsigned long long a,
                                     unsigned long long b) {
    asm("fma.rn.f32x2 %0, %1, %2, %0;" : "+l"(d) : "l"(a), "l"(b));
}
__device__ __forceinline__ void unpk2(unsigned long long v, float& lo, float& hi) {
    asm("mov.b64 {%0, %1}, %2;" : "=f"(lo), "=f"(hi) : "l"(v));
}
__device__ __forceinline__ float sigf(float x) {
    return __fdividef(1.0f, 1.0f + __expf(-x));
}
__device__ __forceinline__ float tanhf_fast(float x) {
    float e = __expf(2.0f * x);
    return 1.0f - __fdividef(2.0f, e + 1.0f);
}

// ---- shared layout (float offsets) -----------------------------------------
#define SBUF      9216          // one [256][36] activation buffer
#define OFF_BUF   0             // 3 buffers: h ping, h pong, p2
#define OFF_C     27648         // [256][36] c state
#define OFF_PREV  36864         // [32][4]
#define OFF_WIH   36992         // [1024][4]
#define OFF_BG    41088         // [1024]
#define OFF_FB1   42112         // [256]
#define OFF_FB2   42368         // [256]
#define OFF_FC3   42624         // [256][4]  fc3T[k][d]
#define OFF_B3    43648         // [4]
#define SMEM_FLOATS 43652
#define SMEM_BYTES  (SMEM_FLOATS * 4)

// fc phase: all 16 warps; thread = units (jf, jf+32) x 8 rows (rf0..rf0+7)
// Weights-first schedule, kk-sliced h, pointer-bumped, unroll 2.
__device__ __forceinline__ void fc_phase(const float* __restrict__ src,
                                         float* __restrict__ dst,
                                         const float4* __restrict__ wbase,
                                         const float* __restrict__ bsh,
                                         int jf, int rf0) {
    unsigned long long acc[2][4];
    {
        float b0 = bsh[jf], b1 = bsh[jf + 32];
        acc[0][0] = acc[0][1] = acc[0][2] = acc[0][3] = pk2(b0, b0);
        acc[1][0] = acc[1][1] = acc[1][2] = acc[1][3] = pk2(b1, b1);
    }
    const float4* wp = wbase + jf;
    const float*  hp = src + rf0;
#pragma unroll 2
    for (int kc = 0; kc < KC; kc++) {
        // weights first: 2 independent LDGs, long distance to use
        float4 w0 = wp[0];
        float4 w1 = wp[32];
        wp += HID;
#pragma unroll
        for (int kk = 0; kk < 4; kk++) {
            ulonglong2 hA = *reinterpret_cast<const ulonglong2*>(hp + kk * 36);
            ulonglong2 hB = *reinterpret_cast<const ulonglong2*>(hp + kk * 36 + 4);
            float a0 = (kk == 0) ? w0.x : (kk == 1) ? w0.y : (kk == 2) ? w0.z : w0.w;
            float a1 = (kk == 0) ? w1.x : (kk == 1) ? w1.y : (kk == 2) ? w1.z : w1.w;
            unsigned long long u0 = pk2(a0, a0);
            unsigned long long u1 = pk2(a1, a1);
            fma2(acc[0][0], u0, hA.x); fma2(acc[0][1], u0, hA.y);
            fma2(acc[0][2], u0, hB.x); fma2(acc[0][3], u0, hB.y);
            fma2(acc[1][0], u1, hA.x); fma2(acc[1][1], u1, hA.y);
            fma2(acc[1][2], u1, hB.x); fma2(acc[1][3], u1, hB.y);
        }
        hp += 144;
    }
#pragma unroll
    for (int u = 0; u < 2; u++) {
        const int j = jf + u * 32;
        float v0, v1, v2, v3, v4, v5, v6, v7;
        unpk2(acc[u][0], v0, v1); unpk2(acc[u][1], v2, v3);
        unpk2(acc[u][2], v4, v5); unpk2(acc[u][3], v6, v7);
        *reinterpret_cast<float4*>(dst + j * 36 + rf0) =
            make_float4(fmaxf(v0, 0.f), fmaxf(v1, 0.f), fmaxf(v2, 0.f), fmaxf(v3, 0.f));
        *reinterpret_cast<float4*>(dst + j * 36 + rf0 + 4) =
            make_float4(fmaxf(v4, 0.f), fmaxf(v5, 0.f), fmaxf(v6, 0.f), fmaxf(v7, 0.f));
    }
}

__global__ void __launch_bounds__(NTHR, 1)
rnn_rollout_kernel(const float* __restrict__ inputs,
                   const float* __restrict__ W_ih,
                   const float* __restrict__ b_ih,
                   const float* __restrict__ b_hh,
                   const float* __restrict__ fc1_b,
                   const float* __restrict__ fc2_b,
                   const float* __restrict__ fc3_w,
                   const float* __restrict__ fc3_b,
                   float* __restrict__ out) {
    extern __shared__ float sm[];
    float* buf    = sm + OFF_BUF;
    float* csh    = sm + OFF_C;
    float* prevsh = sm + OFF_PREV;
    float* wihsh  = sm + OFF_WIH;
    float* bgsh   = sm + OFF_BG;
    float* fb1sh  = sm + OFF_FB1;
    float* fb2sh  = sm + OFF_FB2;
    float* fc3T   = sm + OFF_FC3;
    float* b3sh   = sm + OFF_B3;

    const int tid  = threadIdx.x;
    const int w    = tid >> 5;           // warp 0..15
    const int l    = tid & 31;
    // phase A / elementwise mapping: warp = 32 consecutive j2 x 1 row-half
    const int j2   = (w & 7) * 32 + l;   // 0..255
    const int rh   = w >> 3;             // 0..1
    const int r0   = rh * 16;            // 16 rows per thread
    // fc mapping: thread = units (jf, jf+32) x rows rf0..rf0+7
    const int jf   = (w & 3) * 64 + l;
    const int rf0  = (w >> 2) * 8;
    const int row0 = blockIdx.x * MROWS;

    // ---- one-time init ----
    for (int i = tid; i < G4; i += NTHR) {
        *reinterpret_cast<float4*>(wihsh + i * 4) =
            *reinterpret_cast<const float4*>(W_ih + i * 4);
        bgsh[i] = b_ih[i] + b_hh[i];
        fc3T[i] = fc3_w[(i & 3) * HID + (i >> 2)];
    }
    if (tid < HID) { fb1sh[tid] = fc1_b[tid]; fb2sh[tid] = fc2_b[tid]; }
    if (tid < DIN) b3sh[tid] = fc3_b[tid];
    for (int i = tid; i < 3 * SBUF; i += NTHR) buf[i] = 0.0f;
    for (int i = tid; i < SBUF; i += NTHR) csh[i] = 0.0f;
    if (tid < MROWS * DIN)
        prevsh[tid] = inputs[((size_t)(row0 + (tid >> 2)) * T_STEPS) * DIN + (tid & 3)];
    __syncthreads();

    for (int t = 0; t < T_STEPS; t++) {
        const int par = t & 1;
        float* hin  = buf + par * SBUF;
        float* hout = buf + (par ^ 1) * SBUF;
        float* p1   = hin;                 // fc1 overwrites dead h_in
        float* p2   = buf + 2 * SBUF;

        // ---- phase A: gate GEMM. thread = j2 x 4 gates x 16 rows ----
        unsigned long long acc[4][8];
        {
#pragma unroll
            for (int g = 0; g < 4; g++) {
                float4 wg = *reinterpret_cast<const float4*>(wihsh + (g * 256 + j2) * 4);
                float b = bgsh[g * 256 + j2];
#pragma unroll
                for (int p = 0; p < 8; p++) {
                    float4 pa = *reinterpret_cast<const float4*>(prevsh + 4 * (r0 + 2 * p));
                    float4 pb = *reinterpret_cast<const float4*>(prevsh + 4 * (r0 + 2 * p + 1));
                    acc[g][p] = pk2(b + wg.x*pa.x + wg.y*pa.y + wg.z*pa.z + wg.w*pa.w,
                                    b + wg.x*pb.x + wg.y*pb.y + wg.z*pb.z + wg.w*pb.w);
                }
            }
        }
        {
            const float4* gw = g_whh + j2;
            const float*  hp = hin + r0;
#pragma unroll 2
            for (int kc = 0; kc < KC; kc++) {
                // weights first: 4 independent coalesced LDG.128 (MLP=4)
                float4 wv0 = gw[0];
                float4 wv1 = gw[256];
                float4 wv2 = gw[512];
                float4 wv3 = gw[768];
                gw += G4;
                // h consumed kk-sliced: 16 rows = 4 ulonglong2 per kk
#pragma unroll
                for (int kk = 0; kk < 4; kk++) {
                    const float* hb = hp + kk * 36;
                    ulonglong2 hA = *reinterpret_cast<const ulonglong2*>(hb);
                    ulonglong2 hB = *reinterpret_cast<const ulonglong2*>(hb + 4);
                    ulonglong2 hC = *reinterpret_cast<const ulonglong2*>(hb + 8);
                    ulonglong2 hD = *reinterpret_cast<const ulonglong2*>(hb + 12);
                    float a0 = (kk == 0) ? wv0.x : (kk == 1) ? wv0.y : (kk == 2) ? wv0.z : wv0.w;
                    float a1 = (kk == 0) ? wv1.x : (kk == 1) ? wv1.y : (kk == 2) ? wv1.z : wv1.w;
                    float a2 = (kk == 0) ? wv2.x : (kk == 1) ? wv2.y : (kk == 2) ? wv2.z : wv2.w;
                    float a3 = (kk == 0) ? wv3.x : (kk == 1) ? wv3.y : (kk == 2) ? wv3.z : wv3.w;
                    unsigned long long u0 = pk2(a0, a0);
                    unsigned long long u1 = pk2(a1, a1);
                    unsigned long long u2 = pk2(a2, a2);
                    unsigned long long u3 = pk2(a3, a3);
                    fma2(acc[0][0], u0, hA.x); fma2(acc[0][1], u0, hA.y);
                    fma2(acc[0][2], u0, hB.x); fma2(acc[0][3], u0, hB.y);
                    fma2(acc[0][4], u0, hC.x); fma2(acc[0][5], u0, hC.y);
                    fma2(acc[0][6], u0, hD.x); fma2(acc[0][7], u0, hD.y);
                    fma2(acc[1][0], u1, hA.x); fma2(acc[1][1], u1, hA.y);
                    fma2(acc[1][2], u1, hB.x); fma2(acc[1][3], u1, hB.y);
                    fma2(acc[1][4], u1, hC.x); fma2(acc[1][5], u1, hC.y);
                    fma2(acc[1][6], u1, hD.x); fma2(acc[1][7], u1, hD.y);
                    fma2(acc[2][0], u2, hA.x); fma2(acc[2][1], u2, hA.y);
                    fma2(acc[2][2], u2, hB.x); fma2(acc[2][3], u2, hB.y);
                    fma2(acc[2][4], u2, hC.x); fma2(acc[2][5], u2, hC.y);
                    fma2(acc[2][6], u2, hD.x); fma2(acc[2][7], u2, hD.y);
                    fma2(acc[3][0], u3, hA.x); fma2(acc[3][1], u3, hA.y);
                    fma2(acc[3][2], u3, hB.x); fma2(acc[3][3], u3, hB.y);
                    fma2(acc[3][4], u3, hC.x); fma2(acc[3][5], u3, hC.y);
                    fma2(acc[3][6], u3, hD.x); fma2(acc[3][7], u3, hD.y);
                }
                hp += 144;
            }
        }
        // ---- fused LSTM elementwise: (j2, rows r0..r0+15) ----
        {
            float cc[16];
#pragma unroll
            for (int q = 0; q < 4; q++) {
                float4 cv = *reinterpret_cast<const float4*>(csh + j2 * 36 + r0 + 4 * q);
                cc[4*q] = cv.x; cc[4*q+1] = cv.y; cc[4*q+2] = cv.z; cc[4*q+3] = cv.w;
            }
            float hh[16];
#pragma unroll
            for (int p = 0; p < 8; p++) {
                float i0, i1, f0, f1, g0, g1, o0, o1;
                unpk2(acc[0][p], i0, i1);
                unpk2(acc[1][p], f0, f1);
                unpk2(acc[2][p], g0, g1);
                unpk2(acc[3][p], o0, o1);
                float c0 = sigf(f0) * cc[2*p]   + sigf(i0) * tanhf_fast(g0);
                float c1 = sigf(f1) * cc[2*p+1] + sigf(i1) * tanhf_fast(g1);
                cc[2*p]   = c0;
                cc[2*p+1] = c1;
                hh[2*p]   = sigf(o0) * tanhf_fast(c0);
                hh[2*p+1] = sigf(o1) * tanhf_fast(c1);
            }
#pragma unroll
            for (int q = 0; q < 4; q++) {
                *reinterpret_cast<float4*>(csh + j2 * 36 + r0 + 4 * q) =
                    make_float4(cc[4*q], cc[4*q+1], cc[4*q+2], cc[4*q+3]);
                *reinterpret_cast<float4*>(hout + j2 * 36 + r0 + 4 * q) =
                    make_float4(hh[4*q], hh[4*q+1], hh[4*q+2], hh[4*q+3]);
            }
        }
        __syncthreads();

        // ---- fc1: hout -> p1 (all 16 warps) ----
        fc_phase(hout, p1, g_fc1, fb1sh, jf, rf0);
        __syncthreads();

        // ---- fc2: p1 -> p2 (all 16 warps) ----
        fc_phase(p1, p2, g_fc2, fb2sh, jf, rf0);
        __syncthreads();

        // ---- fc3 + residual: 16 warps, 2 rows each ----
#pragma unroll
        for (int rr = 0; rr < 2; rr++) {
            const int row = 2 * w + rr;
            const int d   = l & 3;
            const int s   = l >> 2;
            const float* pp = p2 + row;
            float a0 = 0.f;
#pragma unroll 8
            for (int i = 0; i < 32; i++) {
                const int k = i * 8 + s;
                a0 = fmaf(pp[k * 36], fc3T[k * 4 + d], a0);
            }
            a0 += __shfl_xor_sync(0xffffffffu, a0, 4);
            a0 += __shfl_xor_sync(0xffffffffu, a0, 8);
            a0 += __shfl_xor_sync(0xffffffffu, a0, 16);
            if (s == 0) {
                float r = a0 + b3sh[d] + prevsh[row * 4 + d];
                out[((size_t)(row0 + row) * T_STEPS + t) * DIN + d] = r;
                prevsh[row * 4 + d] = r;
            }
        }
        __syncthreads();
    }
}

extern "C" void kernel_launch(void* const* d_in, const int* in_sizes, int n_in,
                              void* d_out, int out_size) {
    const float* inputs = (const float*)d_in[0];
    const float* W_ih   = (const float*)d_in[1];
    const float* W_hh   = (const float*)d_in[2];
    const float* b_ih   = (const float*)d_in[3];
    const float* b_hh   = (const float*)d_in[4];
    const float* fc1_w  = (const float*)d_in[5];
    const float* fc1_b  = (const float*)d_in[6];
    const float* fc2_w  = (const float*)d_in[7];
    const float* fc2_b  = (const float*)d_in[8];
    const float* fc3_w  = (const float*)d_in[9];
    const float* fc3_b  = (const float*)d_in[10];
    float* out = (float*)d_out;

    const int pack_threads = 256;
    const int pack_total   = KC * G4;
    pack_kernel<<<(pack_total + pack_threads - 1) / pack_threads, pack_threads>>>(
        W_hh, fc1_w, fc2_w);

    cudaFuncSetAttribute(rnn_rollout_kernel,
                         cudaFuncAttributeMaxDynamicSharedMemorySize, SMEM_BYTES);
    rnn_rollout_kernel<<<NCTA, NTHR, SMEM_BYTES>>>(
        inputs, W_ih, b_ih, b_hh, fc1_b, fc2_b, fc3_w, fc3_b, out);
}

// round 15
// speedup vs baseline: 1.4352x; 1.0252x over previous
#include <cuda_runtime.h>

// ---------------------------------------------------------------------------
// GraphRNNDecoder rollout. N=4096 rows, T=128 steps, D=4, H=256.
// R15: R14 (128 CTAs x 512 thr x 128 regs, 16-row gate blocking) + explicit
// software-pipelined weight prefetch: depth-2 rotation in fc_phase (low FMA
// density -> LDG latency was exposed), depth-1 rotation in phase A.
// Weight arrays padded so prefetch is unpredicated.
// ---------------------------------------------------------------------------

#define T_STEPS 128
#define DIN     4
#define HID     256
#define G4      1024
#define MROWS   32
#define NCTA    128
#define NTHR    512
#define KC      64

// k-chunk packed weights [kc][unit] -> float4 of W[unit][4kc..4kc+3]
// padded by 1-2 kc blocks for unpredicated prefetch overrun
__device__ float4 g_whh[(KC + 1) * G4];
__device__ float4 g_fc1[(KC + 2) * HID];
__device__ float4 g_fc2[(KC + 2) * HID];

__global__ void pack_kernel(const float* __restrict__ W_hh,
                            const float* __restrict__ fc1_w,
                            const float* __restrict__ fc2_w) {
    int i = blockIdx.x * blockDim.x + threadIdx.x;
    if (i < KC * G4) {
        int kc = i >> 10, j = i & 1023;
        g_whh[i] = *reinterpret_cast<const float4*>(W_hh + j * HID + kc * 4);
    }
    if (i < KC * HID) {
        int kc = i >> 8, j = i & 255;
        g_fc1[i] = *reinterpret_cast<const float4*>(fc1_w + j * HID + kc * 4);
        g_fc2[i] = *reinterpret_cast<const float4*>(fc2_w + j * HID + kc * 4);
    }
}

// ---- packed f32x2 helpers --------------------------------------------------
__device__ __forceinline__ unsigned long long pk2(float lo, float hi) {
    unsigned long long r;
    asm("mov.b64 %0, {%1, %2};" : "=l"(r) : "f"(lo), "f"(hi));
    return r;
}
__device__ __forceinline__ void fma2(unsigned long long& d,
                                     unsigned long long a,
                                     unsigned long long b) {
    asm("fma.rn.f32x2 %0, %1, %2, %0;" : "+l"(d) : "l"(a), "l"(b));
}
__device__ __forceinline__ void unpk2(unsigned long long v, float& lo, float& hi) {
    asm("mov.b64 {%0, %1}, %2;" : "=f"(lo), "=f"(hi) : "l"(v));
}
__device__ __forceinline__ float sigf(float x) {
    return __fdividef(1.0f, 1.0f + __expf(-x));
}
__device__ __forceinline__ float tanhf_fast(float x) {
    float e = __expf(2.0f * x);
    return 1.0f - __fdividef(2.0f, e + 1.0f);
}

// ---- shared layout (float offsets) -----------------------------------------
#define SBUF      9216          // one [256][36] activation buffer
#define OFF_BUF   0             // 3 buffers: h ping, h pong, p2
#define OFF_C     27648         // [256][36] c state
#define OFF_PREV  36864         // [32][4]
#define OFF_WIH   36992         // [1024][4]
#define OFF_BG    41088         // [1024]
#define OFF_FB1   42112         // [256]
#define OFF_FB2   42368         // [256]
#define OFF_FC3   42624         // [256][4]  fc3T[k][d]
#define OFF_B3    43648         // [4]
#define SMEM_FLOATS 43652
#define SMEM_BYTES  (SMEM_FLOATS * 4)

// one fc inner body for chunk kc: 2 units x 8 rows
__device__ __forceinline__ void fc_body(unsigned long long acc[2][4],
                                        float4 w0, float4 w1,
                                        const float* __restrict__ hp) {
#pragma unroll
    for (int kk = 0; kk < 4; kk++) {
        ulonglong2 hA = *reinterpret_cast<const ulonglong2*>(hp + kk * 36);
        ulonglong2 hB = *reinterpret_cast<const ulonglong2*>(hp + kk * 36 + 4);
        float a0 = (kk == 0) ? w0.x : (kk == 1) ? w0.y : (kk == 2) ? w0.z : w0.w;
        float a1 = (kk == 0) ? w1.x : (kk == 1) ? w1.y : (kk == 2) ? w1.z : w1.w;
        unsigned long long u0 = pk2(a0, a0);
        unsigned long long u1 = pk2(a1, a1);
        fma2(acc[0][0], u0, hA.x); fma2(acc[0][1], u0, hA.y);
        fma2(acc[0][2], u0, hB.x); fma2(acc[0][3], u0, hB.y);
        fma2(acc[1][0], u1, hA.x); fma2(acc[1][1], u1, hA.y);
        fma2(acc[1][2], u1, hB.x); fma2(acc[1][3], u1, hB.y);
    }
}

// fc phase: all 16 warps; thread = units (jf, jf+32) x 8 rows (rf0..rf0+7)
// Depth-2 software-pipelined weight prefetch.
__device__ __forceinline__ void fc_phase(const float* __restrict__ src,
                                         float* __restrict__ dst,
                                         const float4* __restrict__ wbase,
                                         const float* __restrict__ bsh,
                                         int jf, int rf0) {
    unsigned long long acc[2][4];
    {
        float b0 = bsh[jf], b1 = bsh[jf + 32];
        acc[0][0] = acc[0][1] = acc[0][2] = acc[0][3] = pk2(b0, b0);
        acc[1][0] = acc[1][1] = acc[1][2] = acc[1][3] = pk2(b1, b1);
    }
    const float4* wp = wbase + jf;
    const float*  hp = src + rf0;
    // depth-2 prefetch: wa = kc, wb = kc+1; wp points at kc+2
    float4 wa0 = wp[0],   wa1 = wp[32];
    float4 wb0 = wp[HID], wb1 = wp[HID + 32];
    wp += 2 * HID;
#pragma unroll 1
    for (int kc = 0; kc < KC; kc += 2) {
        // prefetch kc+2, kc+3 (pad region on last iters)
        float4 na0 = wp[0],   na1 = wp[32];
        float4 nb0 = wp[HID], nb1 = wp[HID + 32];
        wp += 2 * HID;
        fc_body(acc, wa0, wa1, hp);
        hp += 144;
        fc_body(acc, wb0, wb1, hp);
        hp += 144;
        wa0 = na0; wa1 = na1; wb0 = nb0; wb1 = nb1;
    }
#pragma unroll
    for (int u = 0; u < 2; u++) {
        const int j = jf + u * 32;
        float v0, v1, v2, v3, v4, v5, v6, v7;
        unpk2(acc[u][0], v0, v1); unpk2(acc[u][1], v2, v3);
        unpk2(acc[u][2], v4, v5); unpk2(acc[u][3], v6, v7);
        *reinterpret_cast<float4*>(dst + j * 36 + rf0) =
            make_float4(fmaxf(v0, 0.f), fmaxf(v1, 0.f), fmaxf(v2, 0.f), fmaxf(v3, 0.f));
        *reinterpret_cast<float4*>(dst + j * 36 + rf0 + 4) =
            make_float4(fmaxf(v4, 0.f), fmaxf(v5, 0.f), fmaxf(v6, 0.f), fmaxf(v7, 0.f));
    }
}

__global__ void __launch_bounds__(NTHR, 1)
rnn_rollout_kernel(const float* __restrict__ inputs,
                   const float* __restrict__ W_ih,
                   const float* __restrict__ b_ih,
                   const float* __restrict__ b_hh,
                   const float* __restrict__ fc1_b,
                   const float* __restrict__ fc2_b,
                   const float* __restrict__ fc3_w,
                   const float* __restrict__ fc3_b,
                   float* __restrict__ out) {
    extern __shared__ float sm[];
    float* buf    = sm + OFF_BUF;
    float* csh    = sm + OFF_C;
    float* prevsh = sm + OFF_PREV;
    float* wihsh  = sm + OFF_WIH;
    float* bgsh   = sm + OFF_BG;
    float* fb1sh  = sm + OFF_FB1;
    float* fb2sh  = sm + OFF_FB2;
    float* fc3T   = sm + OFF_FC3;
    float* b3sh   = sm + OFF_B3;

    const int tid  = threadIdx.x;
    const int w    = tid >> 5;           // warp 0..15
    const int l    = tid & 31;
    // phase A / elementwise mapping: warp = 32 consecutive j2 x 1 row-half
    const int j2   = (w & 7) * 32 + l;   // 0..255
    const int rh   = w >> 3;             // 0..1
    const int r0   = rh * 16;            // 16 rows per thread
    // fc mapping: thread = units (jf, jf+32) x rows rf0..rf0+7
    const int jf   = (w & 3) * 64 + l;
    const int rf0  = (w >> 2) * 8;
    const int row0 = blockIdx.x * MROWS;

    // ---- one-time init ----
    for (int i = tid; i < G4; i += NTHR) {
        *reinterpret_cast<float4*>(wihsh + i * 4) =
            *reinterpret_cast<const float4*>(W_ih + i * 4);
        bgsh[i] = b_ih[i] + b_hh[i];
        fc3T[i] = fc3_w[(i & 3) * HID + (i >> 2)];
    }
    if (tid < HID) { fb1sh[tid] = fc1_b[tid]; fb2sh[tid] = fc2_b[tid]; }
    if (tid < DIN) b3sh[tid] = fc3_b[tid];
    for (int i = tid; i < 3 * SBUF; i += NTHR) buf[i] = 0.0f;
    for (int i = tid; i < SBUF; i += NTHR) csh[i] = 0.0f;
    if (tid < MROWS * DIN)
        prevsh[tid] = inputs[((size_t)(row0 + (tid >> 2)) * T_STEPS) * DIN + (tid & 3)];
    __syncthreads();

    for (int t = 0; t < T_STEPS; t++) {
        const int par = t & 1;
        float* hin  = buf + par * SBUF;
        float* hout = buf + (par ^ 1) * SBUF;
        float* p1   = hin;                 // fc1 overwrites dead h_in
        float* p2   = buf + 2 * SBUF;

        // ---- phase A: gate GEMM. thread = j2 x 4 gates x 16 rows ----
        unsigned long long acc[4][8];
        {
#pragma unroll
            for (int g = 0; g < 4; g++) {
                float4 wg = *reinterpret_cast<const float4*>(wihsh + (g * 256 + j2) * 4);
                float b = bgsh[g * 256 + j2];
#pragma unroll
                for (int p = 0; p < 8; p++) {
                    float4 pa = *reinterpret_cast<const float4*>(prevsh + 4 * (r0 + 2 * p));
                    float4 pb = *reinterpret_cast<const float4*>(prevsh + 4 * (r0 + 2 * p + 1));
                    acc[g][p] = pk2(b + wg.x*pa.x + wg.y*pa.y + wg.z*pa.z + wg.w*pa.w,
                                    b + wg.x*pb.x + wg.y*pb.y + wg.z*pb.z + wg.w*pb.w);
                }
            }
        }
        {
            const float4* gw = g_whh + j2 + G4;   // points at kc+1 block
            const float*  hp = hin + r0;
            // depth-1 prefetch rotation
            float4 wv0 = gw[-G4 + 0];
            float4 wv1 = gw[-G4 + 256];
            float4 wv2 = gw[-G4 + 512];
            float4 wv3 = gw[-G4 + 768];
#pragma unroll 2
            for (int kc = 0; kc < KC; kc++) {
                // prefetch kc+1 (pad block on last iter)
                float4 n0 = gw[0];
                float4 n1 = gw[256];
                float4 n2 = gw[512];
                float4 n3 = gw[768];
                gw += G4;
                // h consumed kk-sliced: 16 rows = 4 ulonglong2 per kk
#pragma unroll
                for (int kk = 0; kk < 4; kk++) {
                    const float* hb = hp + kk * 36;
                    ulonglong2 hA = *reinterpret_cast<const ulonglong2*>(hb);
                    ulonglong2 hB = *reinterpret_cast<const ulonglong2*>(hb + 4);
                    ulonglong2 hC = *reinterpret_cast<const ulonglong2*>(hb + 8);
                    ulonglong2 hD = *reinterpret_cast<const ulonglong2*>(hb + 12);
                    float a0 = (kk == 0) ? wv0.x : (kk == 1) ? wv0.y : (kk == 2) ? wv0.z : wv0.w;
                    float a1 = (kk == 0) ? wv1.x : (kk == 1) ? wv1.y : (kk == 2) ? wv1.z : wv1.w;
                    float a2 = (kk == 0) ? wv2.x : (kk == 1) ? wv2.y : (kk == 2) ? wv2.z : wv2.w;
                    float a3 = (kk == 0) ? wv3.x : (kk == 1) ? wv3.y : (kk == 2) ? wv3.z : wv3.w;
                    unsigned long long u0 = pk2(a0, a0);
                    unsigned long long u1 = pk2(a1, a1);
                    unsigned long long u2 = pk2(a2, a2);
                    unsigned long long u3 = pk2(a3, a3);
                    fma2(acc[0][0], u0, hA.x); fma2(acc[0][1], u0, hA.y);
                    fma2(acc[0][2], u0, hB.x); fma2(acc[0][3], u0, hB.y);
                    fma2(acc[0][4], u0, hC.x); fma2(acc[0][5], u0, hC.y);
                    fma2(acc[0][6], u0, hD.x); fma2(acc[0][7], u0, hD.y);
                    fma2(acc[1][0], u1, hA.x); fma2(acc[1][1], u1, hA.y);
                    fma2(acc[1][2], u1, hB.x); fma2(acc[1][3], u1, hB.y);
                    fma2(acc[1][4], u1, hC.x); fma2(acc[1][5], u1, hC.y);
                    fma2(acc[1][6], u1, hD.x); fma2(acc[1][7], u1, hD.y);
                    fma2(acc[2][0], u2, hA.x); fma2(acc[2][1], u2, hA.y);
                    fma2(acc[2][2], u2, hB.x); fma2(acc[2][3], u2, hB.y);
                    fma2(acc[2][4], u2, hC.x); fma2(acc[2][5], u2, hC.y);
                    fma2(acc[2][6], u2, hD.x); fma2(acc[2][7], u2, hD.y);
                    fma2(acc[3][0], u3, hA.x); fma2(acc[3][1], u3, hA.y);
                    fma2(acc[3][2], u3, hB.x); fma2(acc[3][3], u3, hB.y);
                    fma2(acc[3][4], u3, hC.x); fma2(acc[3][5], u3, hC.y);
                    fma2(acc[3][6], u3, hD.x); fma2(acc[3][7], u3, hD.y);
                }
                hp += 144;
                wv0 = n0; wv1 = n1; wv2 = n2; wv3 = n3;
            }
        }
        // ---- fused LSTM elementwise: (j2, rows r0..r0+15) ----
        {
            float cc[16];
#pragma unroll
            for (int q = 0; q < 4; q++) {
                float4 cv = *reinterpret_cast<const float4*>(csh + j2 * 36 + r0 + 4 * q);
                cc[4*q] = cv.x; cc[4*q+1] = cv.y; cc[4*q+2] = cv.z; cc[4*q+3] = cv.w;
            }
            float hh[16];
#pragma unroll
            for (int p = 0; p < 8; p++) {
                float i0, i1, f0, f1, g0, g1, o0, o1;
                unpk2(acc[0][p], i0, i1);
                unpk2(acc[1][p], f0, f1);
                unpk2(acc[2][p], g0, g1);
                unpk2(acc[3][p], o0, o1);
                float c0 = sigf(f0) * cc[2*p]   + sigf(i0) * tanhf_fast(g0);
                float c1 = sigf(f1) * cc[2*p+1] + sigf(i1) * tanhf_fast(g1);
                cc[2*p]   = c0;
                cc[2*p+1] = c1;
                hh[2*p]   = sigf(o0) * tanhf_fast(c0);
                hh[2*p+1] = sigf(o1) * tanhf_fast(c1);
            }
#pragma unroll
            for (int q = 0; q < 4; q++) {
                *reinterpret_cast<float4*>(csh + j2 * 36 + r0 + 4 * q) =
                    make_float4(cc[4*q], cc[4*q+1], cc[4*q+2], cc[4*q+3]);
                *reinterpret_cast<float4*>(hout + j2 * 36 + r0 + 4 * q) =
                    make_float4(hh[4*q], hh[4*q+1], hh[4*q+2], hh[4*q+3]);
            }
        }
        __syncthreads();

        // ---- fc1: hout -> p1 (all 16 warps) ----
        fc_phase(hout, p1, g_fc1, fb1sh, jf, rf0);
        __syncthreads();

        // ---- fc2: p1 -> p2 (all 16 warps) ----
        fc_phase(p1, p2, g_fc2, fb2sh, jf, rf0);
        __syncthreads();

        // ---- fc3 + residual: 16 warps, 2 rows each ----
#pragma unroll
        for (int rr = 0; rr < 2; rr++) {
            const int row = 2 * w + rr;
            const int d   = l & 3;
            const int s   = l >> 2;
            const float* pp = p2 + row;
            float a0 = 0.f;
#pragma unroll 8
            for (int i = 0; i < 32; i++) {
                const int k = i * 8 + s;
                a0 = fmaf(pp[k * 36], fc3T[k * 4 + d], a0);
            }
            a0 += __shfl_xor_sync(0xffffffffu, a0, 4);
            a0 += __shfl_xor_sync(0xffffffffu, a0, 8);
            a0 += __shfl_xor_sync(0xffffffffu, a0, 16);
            if (s == 0) {
                float r = a0 + b3sh[d] + prevsh[row * 4 + d];
                out[((size_t)(row0 + row) * T_STEPS + t) * DIN + d] = r;
                prevsh[row * 4 + d] = r;
            }
        }
        __syncthreads();
    }
}

extern "C" void kernel_launch(void* const* d_in, const int* in_sizes, int n_in,
                              void* d_out, int out_size) {
    const float* inputs = (const float*)d_in[0];
    const float* W_ih   = (const float*)d_in[1];
    const float* W_hh   = (const float*)d_in[2];
    const float* b_ih   = (const float*)d_in[3];
    const float* b_hh   = (const float*)d_in[4];
    const float* fc1_w  = (const float*)d_in[5];
    const float* fc1_b  = (const float*)d_in[6];
    const float* fc2_w  = (const float*)d_in[7];
    const float* fc2_b  = (const float*)d_in[8];
    const float* fc3_w  = (const float*)d_in[9];
    const float* fc3_b  = (const float*)d_in[10];
    float* out = (float*)d_out;

    const int pack_threads = 256;
    const int pack_total   = KC * G4;
    pack_kernel<<<(pack_total + pack_threads - 1) / pack_threads, pack_threads>>>(
        W_hh, fc1_w, fc2_w);

    cudaFuncSetAttribute(rnn_rollout_kernel,
                         cudaFuncAttributeMaxDynamicSharedMemorySize, SMEM_BYTES);
    rnn_rollout_kernel<<<NCTA, NTHR, SMEM_BYTES>>>(
        inputs, W_ih, b_ih, b_hh, fc1_b, fc2_b, fc3_w, fc3_b, out);
}

// round 16
// speedup vs baseline: 1.5036x; 1.0476x over previous
#include <cuda_runtime.h>

// ---------------------------------------------------------------------------
// GraphRNNDecoder rollout. N=4096 rows, T=128 steps, D=4, H=256.
// R16: R15 engine (128 CTAs x 512 thr x 128 regs, 16-row gate blocking,
// prefetched weights) + CTA split into two independent 16-row halves.
// Warps 0-7 own rows 0-15, warps 8-15 own rows 16-31; all in-loop syncs are
// 256-thread named barriers (bar.sync half+1) -> halves free-run, overlapping
// FMA-dense gate GEMM with LDG-heavy fc phases.
// ---------------------------------------------------------------------------

#define T_STEPS 128
#define DIN     4
#define HID     256
#define G4      1024
#define MROWS   32
#define NCTA    128
#define NTHR    512
#define KC      64

// k-chunk packed weights [kc][unit] -> float4 of W[unit][4kc..4kc+3]
// padded by 1-2 kc blocks for unpredicated prefetch overrun
__device__ float4 g_whh[(KC + 1) * G4];
__device__ float4 g_fc1[(KC + 2) * HID];
__device__ float4 g_fc2[(KC + 2) * HID];

__global__ void pack_kernel(const float* __restrict__ W_hh,
                            const float* __restrict__ fc1_w,
                            const float* __restrict__ fc2_w) {
    int i = blockIdx.x * blockDim.x + threadIdx.x;
    if (i < KC * G4) {
        int kc = i >> 10, j = i & 1023;
        g_whh[i] = *reinterpret_cast<const float4*>(W_hh + j * HID + kc * 4);
    }
    if (i < KC * HID) {
        int kc = i >> 8, j = i & 255;
        g_fc1[i] = *reinterpret_cast<const float4*>(fc1_w + j * HID + kc * 4);
        g_fc2[i] = *reinterpret_cast<const float4*>(fc2_w + j * HID + kc * 4);
    }
}

// ---- packed f32x2 helpers --------------------------------------------------
__device__ __forceinline__ unsigned long long pk2(float lo, float hi) {
    unsigned long long r;
    asm("mov.b64 %0, {%1, %2};" : "=l"(r) : "f"(lo), "f"(hi));
    return r;
}
__device__ __forceinline__ void fma2(unsigned long long& d,
                                     unsigned long long a,
                                     unsigned long long b) {
    asm("fma.rn.f32x2 %0, %1, %2, %0;" : "+l"(d) : "l"(a), "l"(b));
}
__device__ __forceinline__ void unpk2(unsigned long long v, float& lo, float& hi) {
    asm("mov.b64 {%0, %1}, %2;" : "=f"(lo), "=f"(hi) : "l"(v));
}
__device__ __forceinline__ float sigf(float x) {
    return __fdividef(1.0f, 1.0f + __expf(-x));
}
__device__ __forceinline__ float tanhf_fast(float x) {
    float e = __expf(2.0f * x);
    return 1.0f - __fdividef(2.0f, e + 1.0f);
}
__device__ __forceinline__ void bar_half(int half) {
    asm volatile("bar.sync %0, %1;" :: "r"(half + 1), "r"(256) : "memory");
}

// ---- shared layout (float offsets) -----------------------------------------
#define SBUF      9216          // one [256][36] activation buffer
#define OFF_BUF   0             // 3 buffers: h ping, h pong, p2
#define OFF_C     27648         // [256][36] c state
#define OFF_PREV  36864         // [32][4]
#define OFF_WIH   36992         // [1024][4]
#define OFF_BG    41088         // [1024]
#define OFF_FB1   42112         // [256]
#define OFF_FB2   42368         // [256]
#define OFF_FC3   42624         // [256][4]  fc3T[k][d]
#define OFF_B3    43648         // [4]
#define SMEM_FLOATS 43652
#define SMEM_BYTES  (SMEM_FLOATS * 4)

// one fc inner body for chunk kc: 2 units x 8 rows
__device__ __forceinline__ void fc_body(unsigned long long acc[2][4],
                                        float4 w0, float4 w1,
                                        const float* __restrict__ hp) {
#pragma unroll
    for (int kk = 0; kk < 4; kk++) {
        ulonglong2 hA = *reinterpret_cast<const ulonglong2*>(hp + kk * 36);
        ulonglong2 hB = *reinterpret_cast<const ulonglong2*>(hp + kk * 36 + 4);
        float a0 = (kk == 0) ? w0.x : (kk == 1) ? w0.y : (kk == 2) ? w0.z : w0.w;
        float a1 = (kk == 0) ? w1.x : (kk == 1) ? w1.y : (kk == 2) ? w1.z : w1.w;
        unsigned long long u0 = pk2(a0, a0);
        unsigned long long u1 = pk2(a1, a1);
        fma2(acc[0][0], u0, hA.x); fma2(acc[0][1], u0, hA.y);
        fma2(acc[0][2], u0, hB.x); fma2(acc[0][3], u0, hB.y);
        fma2(acc[1][0], u1, hA.x); fma2(acc[1][1], u1, hA.y);
        fma2(acc[1][2], u1, hB.x); fma2(acc[1][3], u1, hB.y);
    }
}

// fc phase within one half: thread = units (jf, jf+32) x 8 rows (rf0..rf0+7)
// Depth-2 software-pipelined weight prefetch.
__device__ __forceinline__ void fc_phase(const float* __restrict__ src,
                                         float* __restrict__ dst,
                                         const float4* __restrict__ wbase,
                                         const float* __restrict__ bsh,
                                         int jf, int rf0) {
    unsigned long long acc[2][4];
    {
        float b0 = bsh[jf], b1 = bsh[jf + 32];
        acc[0][0] = acc[0][1] = acc[0][2] = acc[0][3] = pk2(b0, b0);
        acc[1][0] = acc[1][1] = acc[1][2] = acc[1][3] = pk2(b1, b1);
    }
    const float4* wp = wbase + jf;
    const float*  hp = src + rf0;
    // depth-2 prefetch: wa = kc, wb = kc+1; wp points at kc+2
    float4 wa0 = wp[0],   wa1 = wp[32];
    float4 wb0 = wp[HID], wb1 = wp[HID + 32];
    wp += 2 * HID;
#pragma unroll 1
    for (int kc = 0; kc < KC; kc += 2) {
        // prefetch kc+2, kc+3 (pad region on last iters)
        float4 na0 = wp[0],   na1 = wp[32];
        float4 nb0 = wp[HID], nb1 = wp[HID + 32];
        wp += 2 * HID;
        fc_body(acc, wa0, wa1, hp);
        hp += 144;
        fc_body(acc, wb0, wb1, hp);
        hp += 144;
        wa0 = na0; wa1 = na1; wb0 = nb0; wb1 = nb1;
    }
#pragma unroll
    for (int u = 0; u < 2; u++) {
        const int j = jf + u * 32;
        float v0, v1, v2, v3, v4, v5, v6, v7;
        unpk2(acc[u][0], v0, v1); unpk2(acc[u][1], v2, v3);
        unpk2(acc[u][2], v4, v5); unpk2(acc[u][3], v6, v7);
        *reinterpret_cast<float4*>(dst + j * 36 + rf0) =
            make_float4(fmaxf(v0, 0.f), fmaxf(v1, 0.f), fmaxf(v2, 0.f), fmaxf(v3, 0.f));
        *reinterpret_cast<float4*>(dst + j * 36 + rf0 + 4) =
            make_float4(fmaxf(v4, 0.f), fmaxf(v5, 0.f), fmaxf(v6, 0.f), fmaxf(v7, 0.f));
    }
}

__global__ void __launch_bounds__(NTHR, 1)
rnn_rollout_kernel(const float* __restrict__ inputs,
                   const float* __restrict__ W_ih,
                   const float* __restrict__ b_ih,
                   const float* __restrict__ b_hh,
                   const float* __restrict__ fc1_b,
                   const float* __restrict__ fc2_b,
                   const float* __restrict__ fc3_w,
                   const float* __restrict__ fc3_b,
                   float* __restrict__ out) {
    extern __shared__ float sm[];
    float* buf    = sm + OFF_BUF;
    float* csh    = sm + OFF_C;
    float* prevsh = sm + OFF_PREV;
    float* wihsh  = sm + OFF_WIH;
    float* bgsh   = sm + OFF_BG;
    float* fb1sh  = sm + OFF_FB1;
    float* fb2sh  = sm + OFF_FB2;
    float* fc3T   = sm + OFF_FC3;
    float* b3sh   = sm + OFF_B3;

    const int tid  = threadIdx.x;
    const int w    = tid >> 5;           // warp 0..15
    const int l    = tid & 31;
    const int half = w >> 3;             // 0: rows 0-15, 1: rows 16-31
    const int wh   = w & 7;              // warp within half
    // phase A / elementwise mapping: half's 8 warps = 256 threads = 256 j2
    const int j2   = wh * 32 + l;        // 0..255
    const int r0   = half * 16;          // 16 rows per thread (half's rows)
    // fc mapping within half: thread = units (jf, jf+32) x rows rf0..rf0+7
    const int jf   = (wh & 3) * 64 + l;
    const int rf0  = half * 16 + (wh >> 2) * 8;
    const int row0 = blockIdx.x * MROWS;

    // ---- one-time init ----
    for (int i = tid; i < G4; i += NTHR) {
        *reinterpret_cast<float4*>(wihsh + i * 4) =
            *reinterpret_cast<const float4*>(W_ih + i * 4);
        bgsh[i] = b_ih[i] + b_hh[i];
        fc3T[i] = fc3_w[(i & 3) * HID + (i >> 2)];
    }
    if (tid < HID) { fb1sh[tid] = fc1_b[tid]; fb2sh[tid] = fc2_b[tid]; }
    if (tid < DIN) b3sh[tid] = fc3_b[tid];
    for (int i = tid; i < 3 * SBUF; i += NTHR) buf[i] = 0.0f;
    for (int i = tid; i < SBUF; i += NTHR) csh[i] = 0.0f;
    if (tid < MROWS * DIN)
        prevsh[tid] = inputs[((size_t)(row0 + (tid >> 2)) * T_STEPS) * DIN + (tid & 3)];
    __syncthreads();   // only full-CTA barrier

    for (int t = 0; t < T_STEPS; t++) {
        const int par = t & 1;
        float* hin  = buf + par * SBUF;
        float* hout = buf + (par ^ 1) * SBUF;
        float* p1   = hin;                 // fc1 overwrites dead h_in
        float* p2   = buf + 2 * SBUF;

        // ---- phase A: gate GEMM. thread = j2 x 4 gates x 16 rows (half) ----
        unsigned long long acc[4][8];
        {
#pragma unroll
            for (int g = 0; g < 4; g++) {
                float4 wg = *reinterpret_cast<const float4*>(wihsh + (g * 256 + j2) * 4);
                float b = bgsh[g * 256 + j2];
#pragma unroll
                for (int p = 0; p < 8; p++) {
                    float4 pa = *reinterpret_cast<const float4*>(prevsh + 4 * (r0 + 2 * p));
                    float4 pb = *reinterpret_cast<const float4*>(prevsh + 4 * (r0 + 2 * p + 1));
                    acc[g][p] = pk2(b + wg.x*pa.x + wg.y*pa.y + wg.z*pa.z + wg.w*pa.w,
                                    b + wg.x*pb.x + wg.y*pb.y + wg.z*pb.z + wg.w*pb.w);
                }
            }
        }
        {
            const float4* gw = g_whh + j2 + G4;   // points at kc+1 block
            const float*  hp = hin + r0;
            // depth-1 prefetch rotation
            float4 wv0 = gw[-G4 + 0];
            float4 wv1 = gw[-G4 + 256];
            float4 wv2 = gw[-G4 + 512];
            float4 wv3 = gw[-G4 + 768];
#pragma unroll 2
            for (int kc = 0; kc < KC; kc++) {
                // prefetch kc+1 (pad block on last iter)
                float4 n0 = gw[0];
                float4 n1 = gw[256];
                float4 n2 = gw[512];
                float4 n3 = gw[768];
                gw += G4;
                // h consumed kk-sliced: 16 rows = 4 ulonglong2 per kk
#pragma unroll
                for (int kk = 0; kk < 4; kk++) {
                    const float* hb = hp + kk * 36;
                    ulonglong2 hA = *reinterpret_cast<const ulonglong2*>(hb);
                    ulonglong2 hB = *reinterpret_cast<const ulonglong2*>(hb + 4);
                    ulonglong2 hC = *reinterpret_cast<const ulonglong2*>(hb + 8);
                    ulonglong2 hD = *reinterpret_cast<const ulonglong2*>(hb + 12);
                    float a0 = (kk == 0) ? wv0.x : (kk == 1) ? wv0.y : (kk == 2) ? wv0.z : wv0.w;
                    float a1 = (kk == 0) ? wv1.x : (kk == 1) ? wv1.y : (kk == 2) ? wv1.z : wv1.w;
                    float a2 = (kk == 0) ? wv2.x : (kk == 1) ? wv2.y : (kk == 2) ? wv2.z : wv2.w;
                    float a3 = (kk == 0) ? wv3.x : (kk == 1) ? wv3.y : (kk == 2) ? wv3.z : wv3.w;
                    unsigned long long u0 = pk2(a0, a0);
                    unsigned long long u1 = pk2(a1, a1);
                    unsigned long long u2 = pk2(a2, a2);
                    unsigned long long u3 = pk2(a3, a3);
                    fma2(acc[0][0], u0, hA.x); fma2(acc[0][1], u0, hA.y);
                    fma2(acc[0][2], u0, hB.x); fma2(acc[0][3], u0, hB.y);
                    fma2(acc[0][4], u0, hC.x); fma2(acc[0][5], u0, hC.y);
                    fma2(acc[0][6], u0, hD.x); fma2(acc[0][7], u0, hD.y);
                    fma2(acc[1][0], u1, hA.x); fma2(acc[1][1], u1, hA.y);
                    fma2(acc[1][2], u1, hB.x); fma2(acc[1][3], u1, hB.y);
                    fma2(acc[1][4], u1, hC.x); fma2(acc[1][5], u1, hC.y);
                    fma2(acc[1][6], u1, hD.x); fma2(acc[1][7], u1, hD.y);
                    fma2(acc[2][0], u2, hA.x); fma2(acc[2][1], u2, hA.y);
                    fma2(acc[2][2], u2, hB.x); fma2(acc[2][3], u2, hB.y);
                    fma2(acc[2][4], u2, hC.x); fma2(acc[2][5], u2, hC.y);
                    fma2(acc[2][6], u2, hD.x); fma2(acc[2][7], u2, hD.y);
                    fma2(acc[3][0], u3, hA.x); fma2(acc[3][1], u3, hA.y);
                    fma2(acc[3][2], u3, hB.x); fma2(acc[3][3], u3, hB.y);
                    fma2(acc[3][4], u3, hC.x); fma2(acc[3][5], u3, hC.y);
                    fma2(acc[3][6], u3, hD.x); fma2(acc[3][7], u3, hD.y);
                }
                hp += 144;
                wv0 = n0; wv1 = n1; wv2 = n2; wv3 = n3;
            }
        }
        // ---- fused LSTM elementwise: (j2, rows r0..r0+15) ----
        {
            float cc[16];
#pragma unroll
            for (int q = 0; q < 4; q++) {
                float4 cv = *reinterpret_cast<const float4*>(csh + j2 * 36 + r0 + 4 * q);
                cc[4*q] = cv.x; cc[4*q+1] = cv.y; cc[4*q+2] = cv.z; cc[4*q+3] = cv.w;
            }
            float hh[16];
#pragma unroll
            for (int p = 0; p < 8; p++) {
                float i0, i1, f0, f1, g0, g1, o0, o1;
                unpk2(acc[0][p], i0, i1);
                unpk2(acc[1][p], f0, f1);
                unpk2(acc[2][p], g0, g1);
                unpk2(acc[3][p], o0, o1);
                float c0 = sigf(f0) * cc[2*p]   + sigf(i0) * tanhf_fast(g0);
                float c1 = sigf(f1) * cc[2*p+1] + sigf(i1) * tanhf_fast(g1);
                cc[2*p]   = c0;
                cc[2*p+1] = c1;
                hh[2*p]   = sigf(o0) * tanhf_fast(c0);
                hh[2*p+1] = sigf(o1) * tanhf_fast(c1);
            }
#pragma unroll
            for (int q = 0; q < 4; q++) {
                *reinterpret_cast<float4*>(csh + j2 * 36 + r0 + 4 * q) =
                    make_float4(cc[4*q], cc[4*q+1], cc[4*q+2], cc[4*q+3]);
                *reinterpret_cast<float4*>(hout + j2 * 36 + r0 + 4 * q) =
                    make_float4(hh[4*q], hh[4*q+1], hh[4*q+2], hh[4*q+3]);
            }
        }
        bar_half(half);

        // ---- fc1: hout -> p1 (half's 8 warps) ----
        fc_phase(hout, p1, g_fc1, fb1sh, jf, rf0);
        bar_half(half);

        // ---- fc2: p1 -> p2 (half's 8 warps) ----
        fc_phase(p1, p2, g_fc2, fb2sh, jf, rf0);
        bar_half(half);

        // ---- fc3 + residual: half's 8 warps, 2 rows each ----
#pragma unroll
        for (int rr = 0; rr < 2; rr++) {
            const int row = half * 16 + wh * 2 + rr;
            const int d   = l & 3;
            const int s   = l >> 2;
            const float* pp = p2 + row;
            float a0 = 0.f;
#pragma unroll 8
            for (int i = 0; i < 32; i++) {
                const int k = i * 8 + s;
                a0 = fmaf(pp[k * 36], fc3T[k * 4 + d], a0);
            }
            a0 += __shfl_xor_sync(0xffffffffu, a0, 4);
            a0 += __shfl_xor_sync(0xffffffffu, a0, 8);
            a0 += __shfl_xor_sync(0xffffffffu, a0, 16);
            if (s == 0) {
                float r = a0 + b3sh[d] + prevsh[row * 4 + d];
                out[((size_t)(row0 + row) * T_STEPS + t) * DIN + d] = r;
                prevsh[row * 4 + d] = r;
            }
        }
        bar_half(half);
    }
}

extern "C" void kernel_launch(void* const* d_in, const int* in_sizes, int n_in,
                              void* d_out, int out_size) {
    const float* inputs = (const float*)d_in[0];
    const float* W_ih   = (const float*)d_in[1];
    const float* W_hh   = (const float*)d_in[2];
    const float* b_ih   = (const float*)d_in[3];
    const float* b_hh   = (const float*)d_in[4];
    const float* fc1_w  = (const float*)d_in[5];
    const float* fc1_b  = (const float*)d_in[6];
    const float* fc2_w  = (const float*)d_in[7];
    const float* fc2_b  = (const float*)d_in[8];
    const float* fc3_w  = (const float*)d_in[9];
    const float* fc3_b  = (const float*)d_in[10];
    float* out = (float*)d_out;

    const int pack_threads = 256;
    const int pack_total   = KC * G4;
    pack_kernel<<<(pack_total + pack_threads - 1) / pack_threads, pack_threads>>>(
        W_hh, fc1_w, fc2_w);

    cudaFuncSetAttribute(rnn_rollout_kernel,
                         cudaFuncAttributeMaxDynamicSharedMemorySize, SMEM_BYTES);
    rnn_rollout_kernel<<<NCTA, NTHR, SMEM_BYTES>>>(
        inputs, W_ih, b_ih, b_hh, fc1_b, fc2_b, fc3_w, fc3_b, out);
}

// round 17
// speedup vs baseline: 1.6728x; 1.1126x over previous
#include <cuda_runtime.h>

// ---------------------------------------------------------------------------
// GraphRNNDecoder rollout. N=4096 rows, T=128 steps, D=4, H=256.
// R17: occupancy-exact partition: 147 CTAs x 28 rows (halves of 14) on 148
// SMs -- makespan 32->28 rows (-12.5% row-scaled work). f32x2 pair
// granularity (acc[4][7], u64 broadcast h loads, float2 stores). fc splits
// each half into 8-row (4-pair) and 6-row (3-pair) groups. tanh.approx.f32
// for all transcendentals. R16 engine otherwise (512 thr, 128 regs, halves
// free-running on named barriers, prefetched weights).
// ---------------------------------------------------------------------------

#define T_STEPS 128
#define DIN     4
#define HID     256
#define G4      1024
#define NTOT    4096
#define NROWS   28            // rows per CTA
#define RPH     14            // rows per half
#define NPA     7             // row-pairs per half (phase A)
#define NCTA    147
#define NTHR    512
#define KC      64

// k-chunk packed weights [kc][unit] -> float4 of W[unit][4kc..4kc+3]
// padded by 1-2 kc blocks for unpredicated prefetch overrun
__device__ float4 g_whh[(KC + 1) * G4];
__device__ float4 g_fc1[(KC + 2) * HID];
__device__ float4 g_fc2[(KC + 2) * HID];

__global__ void pack_kernel(const float* __restrict__ W_hh,
                            const float* __restrict__ fc1_w,
                            const float* __restrict__ fc2_w) {
    int i = blockIdx.x * blockDim.x + threadIdx.x;
    if (i < KC * G4) {
        int kc = i >> 10, j = i & 1023;
        g_whh[i] = *reinterpret_cast<const float4*>(W_hh + j * HID + kc * 4);
    }
    if (i < KC * HID) {
        int kc = i >> 8, j = i & 255;
        g_fc1[i] = *reinterpret_cast<const float4*>(fc1_w + j * HID + kc * 4);
        g_fc2[i] = *reinterpret_cast<const float4*>(fc2_w + j * HID + kc * 4);
    }
}

// ---- packed f32x2 helpers --------------------------------------------------
__device__ __forceinline__ unsigned long long pk2(float lo, float hi) {
    unsigned long long r;
    asm("mov.b64 %0, {%1, %2};" : "=l"(r) : "f"(lo), "f"(hi));
    return r;
}
__device__ __forceinline__ void fma2(unsigned long long& d,
                                     unsigned long long a,
                                     unsigned long long b) {
    asm("fma.rn.f32x2 %0, %1, %2, %0;" : "+l"(d) : "l"(a), "l"(b));
}
__device__ __forceinline__ void unpk2(unsigned long long v, float& lo, float& hi) {
    asm("mov.b64 {%0, %1}, %2;" : "=f"(lo), "=f"(hi) : "l"(v));
}
__device__ __forceinline__ float tanh_hw(float x) {
    float y;
    asm("tanh.approx.f32 %0, %1;" : "=f"(y) : "f"(x));
    return y;
}
__device__ __forceinline__ float sigf(float x) {
    return fmaf(tanh_hw(0.5f * x), 0.5f, 0.5f);
}
__device__ __forceinline__ void bar_half(int half) {
    asm volatile("bar.sync %0, %1;" :: "r"(half + 1), "r"(256) : "memory");
}

// ---- shared layout (float offsets) -----------------------------------------
#define SBUF      9216          // one [256][36] activation buffer (rows 0..27 used)
#define OFF_BUF   0             // 3 buffers: h ping, h pong, p2
#define OFF_C     27648         // [256][36] c state
#define OFF_PREV  36864         // [32][4] (28 used)
#define OFF_WIH   36992         // [1024][4]
#define OFF_BG    41088         // [1024]
#define OFF_FB1   42112         // [256]
#define OFF_FB2   42368         // [256]
#define OFF_FC3   42624         // [256][4]  fc3T[k][d]
#define OFF_B3    43648         // [4]
#define SMEM_FLOATS 43652
#define SMEM_BYTES  (SMEM_FLOATS * 4)

// fc phase within one half: thread = units (jf, jf+32) x NP row-pairs from rf0.
// Depth-2 software-pipelined weight prefetch. u64 broadcast h loads.
template <int NP>
__device__ __forceinline__ void fc_phase(const float* __restrict__ src,
                                         float* __restrict__ dst,
                                         const float4* __restrict__ wbase,
                                         const float* __restrict__ bsh,
                                         int jf, int rf0) {
    unsigned long long acc[2][NP];
    {
        float b0 = bsh[jf], b1 = bsh[jf + 32];
#pragma unroll
        for (int p = 0; p < NP; p++) { acc[0][p] = pk2(b0, b0); acc[1][p] = pk2(b1, b1); }
    }
    const float4* wp = wbase + jf;
    const float*  hp = src + rf0;
    float4 wa0 = wp[0],   wa1 = wp[32];
    float4 wb0 = wp[HID], wb1 = wp[HID + 32];
    wp += 2 * HID;
#pragma unroll 1
    for (int kc = 0; kc < KC; kc += 2) {
        float4 na0 = wp[0],   na1 = wp[32];
        float4 nb0 = wp[HID], nb1 = wp[HID + 32];
        wp += 2 * HID;
#pragma unroll
        for (int sub = 0; sub < 2; sub++) {
            float4 w0 = (sub == 0) ? wa0 : wb0;
            float4 w1 = (sub == 0) ? wa1 : wb1;
#pragma unroll
            for (int kk = 0; kk < 4; kk++) {
                const float* hb = hp + kk * 36;
                unsigned long long h[NP];
#pragma unroll
                for (int p = 0; p < NP; p++)
                    h[p] = *reinterpret_cast<const unsigned long long*>(hb + 2 * p);
                float a0 = (kk == 0) ? w0.x : (kk == 1) ? w0.y : (kk == 2) ? w0.z : w0.w;
                float a1 = (kk == 0) ? w1.x : (kk == 1) ? w1.y : (kk == 2) ? w1.z : w1.w;
                unsigned long long u0 = pk2(a0, a0);
                unsigned long long u1 = pk2(a1, a1);
#pragma unroll
                for (int p = 0; p < NP; p++) {
                    fma2(acc[0][p], u0, h[p]);
                    fma2(acc[1][p], u1, h[p]);
                }
            }
            hp += 144;
        }
        wa0 = na0; wa1 = na1; wb0 = nb0; wb1 = nb1;
    }
#pragma unroll
    for (int u = 0; u < 2; u++) {
        const int j = jf + u * 32;
#pragma unroll
        for (int p = 0; p < NP; p++) {
            float lo, hi; unpk2(acc[u][p], lo, hi);
            float2 v = make_float2(fmaxf(lo, 0.f), fmaxf(hi, 0.f));
            *reinterpret_cast<float2*>(dst + j * 36 + rf0 + 2 * p) = v;
        }
    }
}

__global__ void __launch_bounds__(NTHR, 1)
rnn_rollout_kernel(const float* __restrict__ inputs,
                   const float* __restrict__ W_ih,
                   const float* __restrict__ b_ih,
                   const float* __restrict__ b_hh,
                   const float* __restrict__ fc1_b,
                   const float* __restrict__ fc2_b,
                   const float* __restrict__ fc3_w,
                   const float* __restrict__ fc3_b,
                   float* __restrict__ out) {
    extern __shared__ float sm[];
    float* buf    = sm + OFF_BUF;
    float* csh    = sm + OFF_C;
    float* prevsh = sm + OFF_PREV;
    float* wihsh  = sm + OFF_WIH;
    float* bgsh   = sm + OFF_BG;
    float* fb1sh  = sm + OFF_FB1;
    float* fb2sh  = sm + OFF_FB2;
    float* fc3T   = sm + OFF_FC3;
    float* b3sh   = sm + OFF_B3;

    const int tid  = threadIdx.x;
    const int w    = tid >> 5;           // warp 0..15
    const int l    = tid & 31;
    const int half = w >> 3;             // 0: rows 0-13, 1: rows 14-27
    const int wh   = w & 7;              // warp within half
    const int j2   = wh * 32 + l;        // 0..255 (phase A unit)
    const int r0   = half * RPH;         // half's row base
    // fc mapping within half: units (jf, jf+32); row group by wh>>2
    const int jf   = (wh & 3) * 64 + l;
    const int fcg  = wh >> 2;            // 0: rows +0..7 (4 pairs), 1: +8..13 (3 pairs)
    const int row0 = blockIdx.x * NROWS;

    // ---- one-time init ----
    for (int i = tid; i < G4; i += NTHR) {
        *reinterpret_cast<float4*>(wihsh + i * 4) =
            *reinterpret_cast<const float4*>(W_ih + i * 4);
        bgsh[i] = b_ih[i] + b_hh[i];
        fc3T[i] = fc3_w[(i & 3) * HID + (i >> 2)];
    }
    if (tid < HID) { fb1sh[tid] = fc1_b[tid]; fb2sh[tid] = fc2_b[tid]; }
    if (tid < DIN) b3sh[tid] = fc3_b[tid];
    for (int i = tid; i < 3 * SBUF; i += NTHR) buf[i] = 0.0f;
    for (int i = tid; i < SBUF; i += NTHR) csh[i] = 0.0f;
    for (int i = tid; i < 32 * DIN; i += NTHR) prevsh[i] = 0.0f;
    __syncthreads();
    if (tid < NROWS * DIN) {
        const int n = tid >> 2;
        if (row0 + n < NTOT)
            prevsh[tid] = inputs[((size_t)(row0 + n) * T_STEPS) * DIN + (tid & 3)];
    }
    __syncthreads();   // only full-CTA barriers (init)

    for (int t = 0; t < T_STEPS; t++) {
        const int par = t & 1;
        float* hin  = buf + par * SBUF;
        float* hout = buf + (par ^ 1) * SBUF;
        float* p1   = hin;                 // fc1 overwrites dead h_in
        float* p2   = buf + 2 * SBUF;

        // ---- phase A: gate GEMM. thread = j2 x 4 gates x 14 rows ----
        unsigned long long acc[4][NPA];
        {
#pragma unroll
            for (int g = 0; g < 4; g++) {
                float4 wg = *reinterpret_cast<const float4*>(wihsh + (g * 256 + j2) * 4);
                float b = bgsh[g * 256 + j2];
#pragma unroll
                for (int p = 0; p < NPA; p++) {
                    float4 pa = *reinterpret_cast<const float4*>(prevsh + 4 * (r0 + 2 * p));
                    float4 pb = *reinterpret_cast<const float4*>(prevsh + 4 * (r0 + 2 * p + 1));
                    acc[g][p] = pk2(b + wg.x*pa.x + wg.y*pa.y + wg.z*pa.z + wg.w*pa.w,
                                    b + wg.x*pb.x + wg.y*pb.y + wg.z*pb.z + wg.w*pb.w);
                }
            }
        }
        {
            const float4* gw = g_whh + j2 + G4;   // points at kc+1 block
            const float*  hp = hin + r0;
            float4 wv0 = gw[-G4 + 0];
            float4 wv1 = gw[-G4 + 256];
            float4 wv2 = gw[-G4 + 512];
            float4 wv3 = gw[-G4 + 768];
#pragma unroll 2
            for (int kc = 0; kc < KC; kc++) {
                float4 n0 = gw[0];
                float4 n1 = gw[256];
                float4 n2 = gw[512];
                float4 n3 = gw[768];
                gw += G4;
#pragma unroll
                for (int kk = 0; kk < 4; kk++) {
                    const float* hb = hp + kk * 36;
                    unsigned long long h[NPA];
#pragma unroll
                    for (int p = 0; p < NPA; p++)
                        h[p] = *reinterpret_cast<const unsigned long long*>(hb + 2 * p);
                    float a0 = (kk == 0) ? wv0.x : (kk == 1) ? wv0.y : (kk == 2) ? wv0.z : wv0.w;
                    float a1 = (kk == 0) ? wv1.x : (kk == 1) ? wv1.y : (kk == 2) ? wv1.z : wv1.w;
                    float a2 = (kk == 0) ? wv2.x : (kk == 1) ? wv2.y : (kk == 2) ? wv2.z : wv2.w;
                    float a3 = (kk == 0) ? wv3.x : (kk == 1) ? wv3.y : (kk == 2) ? wv3.z : wv3.w;
                    unsigned long long u0 = pk2(a0, a0);
                    unsigned long long u1 = pk2(a1, a1);
                    unsigned long long u2 = pk2(a2, a2);
                    unsigned long long u3 = pk2(a3, a3);
#pragma unroll
                    for (int p = 0; p < NPA; p++) {
                        fma2(acc[0][p], u0, h[p]);
                        fma2(acc[1][p], u1, h[p]);
                        fma2(acc[2][p], u2, h[p]);
                        fma2(acc[3][p], u3, h[p]);
                    }
                }
                hp += 144;
                wv0 = n0; wv1 = n1; wv2 = n2; wv3 = n3;
            }
        }
        // ---- fused LSTM elementwise: (j2, rows r0..r0+13) ----
        {
#pragma unroll
            for (int p = 0; p < NPA; p++) {
                float2 cv = *reinterpret_cast<const float2*>(csh + j2 * 36 + r0 + 2 * p);
                float i0, i1, f0, f1, g0, g1, o0, o1;
                unpk2(acc[0][p], i0, i1);
                unpk2(acc[1][p], f0, f1);
                unpk2(acc[2][p], g0, g1);
                unpk2(acc[3][p], o0, o1);
                float c0 = sigf(f0) * cv.x + sigf(i0) * tanh_hw(g0);
                float c1 = sigf(f1) * cv.y + sigf(i1) * tanh_hw(g1);
                *reinterpret_cast<float2*>(csh + j2 * 36 + r0 + 2 * p) =
                    make_float2(c0, c1);
                *reinterpret_cast<float2*>(hout + j2 * 36 + r0 + 2 * p) =
                    make_float2(sigf(o0) * tanh_hw(c0), sigf(o1) * tanh_hw(c1));
            }
        }
        bar_half(half);

        // ---- fc1: hout -> p1 (half's 8 warps; row groups 4-pair / 3-pair) ----
        if (fcg == 0) fc_phase<4>(hout, p1, g_fc1, fb1sh, jf, r0);
        else          fc_phase<3>(hout, p1, g_fc1, fb1sh, jf, r0 + 8);
        bar_half(half);

        // ---- fc2: p1 -> p2 ----
        if (fcg == 0) fc_phase<4>(p1, p2, g_fc2, fb2sh, jf, r0);
        else          fc_phase<3>(p1, p2, g_fc2, fb2sh, jf, r0 + 8);
        bar_half(half);

        // ---- fc3 + residual: warps wh 0..6 handle 2 rows each (14 rows) ----
        if (wh < 7) {
#pragma unroll
            for (int rr = 0; rr < 2; rr++) {
                const int row = r0 + wh * 2 + rr;
                const int d   = l & 3;
                const int s   = l >> 2;
                const float* pp = p2 + row;
                float a0 = 0.f;
#pragma unroll 8
                for (int i = 0; i < 32; i++) {
                    const int k = i * 8 + s;
                    a0 = fmaf(pp[k * 36], fc3T[k * 4 + d], a0);
                }
                a0 += __shfl_xor_sync(0xffffffffu, a0, 4);
                a0 += __shfl_xor_sync(0xffffffffu, a0, 8);
                a0 += __shfl_xor_sync(0xffffffffu, a0, 16);
                if (s == 0) {
                    float r = a0 + b3sh[d] + prevsh[row * 4 + d];
                    if (row0 + row < NTOT)
                        out[((size_t)(row0 + row) * T_STEPS + t) * DIN + d] = r;
                    prevsh[row * 4 + d] = r;
                }
            }
        }
        bar_half(half);
    }
}

extern "C" void kernel_launch(void* const* d_in, const int* in_sizes, int n_in,
                              void* d_out, int out_size) {
    const float* inputs = (const float*)d_in[0];
    const float* W_ih   = (const float*)d_in[1];
    const float* W_hh   = (const float*)d_in[2];
    const float* b_ih   = (const float*)d_in[3];
    const float* b_hh   = (const float*)d_in[4];
    const float* fc1_w  = (const float*)d_in[5];
    const float* fc1_b  = (const float*)d_in[6];
    const float* fc2_w  = (const float*)d_in[7];
    const float* fc2_b  = (const float*)d_in[8];
    const float* fc3_w  = (const float*)d_in[9];
    const float* fc3_b  = (const float*)d_in[10];
    float* out = (float*)d_out;

    const int pack_threads = 256;
    const int pack_total   = KC * G4;
    pack_kernel<<<(pack_total + pack_threads - 1) / pack_threads, pack_threads>>>(
        W_hh, fc1_w, fc2_w);

    cudaFuncSetAttribute(rnn_rollout_kernel,
                         cudaFuncAttributeMaxDynamicSharedMemorySize, SMEM_BYTES);
    rnn_rollout_kernel<<<NCTA, NTHR, SMEM_BYTES>>>(
        inputs, W_ih, b_ih, b_hh, fc1_b, fc2_b, fc3_w, fc3_b, out);
}